// round 1
// baseline (speedup 1.0000x reference)
#include <cuda_runtime.h>
#include <cstdint>
#include <cstddef>

#define B_SZ   8
#define LQ_    2048
#define LKV_   1024
#define DMODEL 1024
#define IMGM   512
#define HEADS_ 16
#define DK_    64

// ---------------- scratch (no allocations allowed) ----------------
__device__ float g_Qp[(size_t)B_SZ * LQ_  * DMODEL];  // 64 MB
__device__ float g_Kp[(size_t)B_SZ * LKV_ * DMODEL];  // 32 MB
__device__ float g_Vp[(size_t)B_SZ * LKV_ * DMODEL];  // 32 MB
__device__ float g_AO[(size_t)B_SZ * LQ_  * DMODEL];  // 64 MB

// ---------------- helpers ----------------
__device__ __forceinline__ float to_tf32(float x) {
    float r;
    asm("cvt.rna.tf32.f32 %0, %1;" : "=f"(r) : "f"(x));
    return r;
}

__device__ __forceinline__ void mma_tf32(float d[4], const unsigned a[4],
                                         unsigned b0, unsigned b1) {
    asm volatile(
        "mma.sync.aligned.m16n8k8.row.col.f32.tf32.tf32.f32 "
        "{%0,%1,%2,%3}, {%4,%5,%6,%7}, {%8,%9}, {%0,%1,%2,%3};"
        : "+f"(d[0]), "+f"(d[1]), "+f"(d[2]), "+f"(d[3])
        : "r"(a[0]), "r"(a[1]), "r"(a[2]), "r"(a[3]), "r"(b0), "r"(b1));
}

// ---------------- generic GEMM:  C[M,N] = A[M,K] @ B[K,N] + bias ----------------
// Block tile 128x128, K-tile 32, 256 threads = 8 warps (4 along M x 2 along N).
// Warp tile 32x64 = 2 x 8 m16n8 tiles. All dims divisible by tile sizes here.
__global__ __launch_bounds__(256) void gemm_bias_tf32(
    const float* __restrict__ A, const float* __restrict__ Bm,
    const float* __restrict__ bias, float* __restrict__ C,
    int M, int N, int K)
{
    __shared__ float As[128 * 36];   // stride 36 -> conflict-free frag loads
    __shared__ float Bs[32 * 136];   // stride 136 -> conflict-free frag loads

    const int tid  = threadIdx.x;
    const int warp = tid >> 5, lane = tid & 31;
    const int wm = warp & 3, wn = warp >> 2;
    const int g = lane >> 2, c = lane & 3;
    const int m0 = blockIdx.y * 128, n0 = blockIdx.x * 128;

    float acc[2][8][4];
#pragma unroll
    for (int i = 0; i < 2; i++)
#pragma unroll
        for (int j = 0; j < 8; j++)
#pragma unroll
            for (int t = 0; t < 4; t++) acc[i][j][t] = 0.f;

    const unsigned* Asu = reinterpret_cast<const unsigned*>(As);
    const unsigned* Bsu = reinterpret_cast<const unsigned*>(Bs);

    for (int k0 = 0; k0 < K; k0 += 32) {
        // load A tile 128x32 (coalesced float4), tf32-round on the way in
#pragma unroll
        for (int p = 0; p < 4; p++) {
            int row = (tid >> 3) + p * 32;
            int col = (tid & 7) * 4;
            float4 v = *reinterpret_cast<const float4*>(
                A + (size_t)(m0 + row) * K + k0 + col);
            v.x = to_tf32(v.x); v.y = to_tf32(v.y);
            v.z = to_tf32(v.z); v.w = to_tf32(v.w);
            *reinterpret_cast<float4*>(As + row * 36 + col) = v;
        }
        // load B tile 32x128
#pragma unroll
        for (int p = 0; p < 4; p++) {
            int row = (tid >> 5) + p * 8;
            int col = (tid & 31) * 4;
            float4 v = *reinterpret_cast<const float4*>(
                Bm + (size_t)(k0 + row) * N + n0 + col);
            v.x = to_tf32(v.x); v.y = to_tf32(v.y);
            v.z = to_tf32(v.z); v.w = to_tf32(v.w);
            *reinterpret_cast<float4*>(Bs + row * 136 + col) = v;
        }
        __syncthreads();

#pragma unroll
        for (int kk = 0; kk < 32; kk += 8) {
            unsigned af[2][4];
#pragma unroll
            for (int mt = 0; mt < 2; mt++) {
                int r = wm * 32 + mt * 16 + g;
                af[mt][0] = Asu[r * 36 + kk + c];
                af[mt][1] = Asu[(r + 8) * 36 + kk + c];
                af[mt][2] = Asu[r * 36 + kk + c + 4];
                af[mt][3] = Asu[(r + 8) * 36 + kk + c + 4];
            }
#pragma unroll
            for (int nt = 0; nt < 8; nt++) {
                int ncol   = wn * 64 + nt * 8 + g;
                unsigned b0 = Bsu[(kk + c) * 136 + ncol];
                unsigned b1 = Bsu[(kk + c + 4) * 136 + ncol];
                mma_tf32(acc[0][nt], af[0], b0, b1);
                mma_tf32(acc[1][nt], af[1], b0, b1);
            }
        }
        __syncthreads();
    }

    // epilogue: += bias, write fp32
#pragma unroll
    for (int mt = 0; mt < 2; mt++) {
        int row = m0 + wm * 32 + mt * 16 + g;
#pragma unroll
        for (int nt = 0; nt < 8; nt++) {
            int col = n0 + wn * 64 + nt * 8 + 2 * c;
            float2 bv = *reinterpret_cast<const float2*>(bias + col);
            float2 r0 = make_float2(acc[mt][nt][0] + bv.x, acc[mt][nt][1] + bv.y);
            float2 r1 = make_float2(acc[mt][nt][2] + bv.x, acc[mt][nt][3] + bv.y);
            *reinterpret_cast<float2*>(C + (size_t)row * N + col)       = r0;
            *reinterpret_cast<float2*>(C + (size_t)(row + 8) * N + col) = r1;
        }
    }
}

// ---------------- flash attention ----------------
// One block = one (b, h, 64-row Q tile). 128 threads = 4 warps; warp w owns
// Q rows [w*16, w*16+16). Online softmax over 16 KV tiles of 64.
// smem: Ks[64][68] | Vs[64][68] | Ps[64][68] (Ps doubles as Q staging).
__global__ __launch_bounds__(128) void flash_attn_tf32(
    const float* __restrict__ Qp, const float* __restrict__ Kp,
    const float* __restrict__ Vp, float* __restrict__ AO)
{
    extern __shared__ float sm[];
    float* Ks = sm;
    float* Vs = sm + 64 * 68;
    float* Ps = sm + 2 * 64 * 68;
    unsigned* Ksu = reinterpret_cast<unsigned*>(Ks);
    unsigned* Vsu = reinterpret_cast<unsigned*>(Vs);
    unsigned* Psu = reinterpret_cast<unsigned*>(Ps);

    const int tid = threadIdx.x;
    const int w = tid >> 5, lane = tid & 31;
    const int g = lane >> 2, c = lane & 3;
    const int qt = blockIdx.x, h = blockIdx.y, b = blockIdx.z;
    const int q0 = qt * 64;

    // ---- stage Q tile into Ps, extract warp's A fragments into registers ----
    const float* Qbase = Qp + ((size_t)(b * LQ_ + q0)) * DMODEL + h * DK_;
#pragma unroll
    for (int p = 0; p < 8; p++) {
        int row = (tid >> 4) + p * 8;
        int col = (tid & 15) * 4;
        float4 v = *reinterpret_cast<const float4*>(Qbase + (size_t)row * DMODEL + col);
        v.x = to_tf32(v.x); v.y = to_tf32(v.y);
        v.z = to_tf32(v.z); v.w = to_tf32(v.w);
        *reinterpret_cast<float4*>(Ps + row * 68 + col) = v;
    }
    __syncthreads();

    unsigned qa[8][4];
    const int prow = w * 16 + g;
#pragma unroll
    for (int kk = 0; kk < 8; kk++) {
        qa[kk][0] = Psu[prow * 68 + kk * 8 + c];
        qa[kk][1] = Psu[(prow + 8) * 68 + kk * 8 + c];
        qa[kk][2] = Psu[prow * 68 + kk * 8 + c + 4];
        qa[kk][3] = Psu[(prow + 8) * 68 + kk * 8 + c + 4];
    }
    __syncthreads();

    float o[8][4];
#pragma unroll
    for (int i = 0; i < 8; i++)
#pragma unroll
        for (int j = 0; j < 4; j++) o[i][j] = 0.f;

    float m_r = -1e30f, m_8 = -1e30f, l_r = 0.f, l_8 = 0.f;
    const float scale = 0.125f;  // 1/sqrt(64)

    const float* Kbase = Kp + ((size_t)(b * LKV_)) * DMODEL + h * DK_;
    const float* Vbase = Vp + ((size_t)(b * LKV_)) * DMODEL + h * DK_;

    for (int kv0 = 0; kv0 < LKV_; kv0 += 64) {
        // ---- stage K,V tiles ----
#pragma unroll
        for (int p = 0; p < 8; p++) {
            int row = (tid >> 4) + p * 8;
            int col = (tid & 15) * 4;
            float4 kv = *reinterpret_cast<const float4*>(
                Kbase + (size_t)(kv0 + row) * DMODEL + col);
            kv.x = to_tf32(kv.x); kv.y = to_tf32(kv.y);
            kv.z = to_tf32(kv.z); kv.w = to_tf32(kv.w);
            *reinterpret_cast<float4*>(Ks + row * 68 + col) = kv;
            float4 vv = *reinterpret_cast<const float4*>(
                Vbase + (size_t)(kv0 + row) * DMODEL + col);
            vv.x = to_tf32(vv.x); vv.y = to_tf32(vv.y);
            vv.z = to_tf32(vv.z); vv.w = to_tf32(vv.w);
            *reinterpret_cast<float4*>(Vs + row * 68 + col) = vv;
        }
        __syncthreads();

        // ---- S = Q @ K^T (k-dim = d, n-dim = kv) ----
        float s[8][4];
#pragma unroll
        for (int i = 0; i < 8; i++)
#pragma unroll
            for (int j = 0; j < 4; j++) s[i][j] = 0.f;
#pragma unroll
        for (int nt = 0; nt < 8; nt++) {
#pragma unroll
            for (int kk = 0; kk < 8; kk++) {
                unsigned b0 = Ksu[(nt * 8 + g) * 68 + kk * 8 + c];
                unsigned b1 = Ksu[(nt * 8 + g) * 68 + kk * 8 + c + 4];
                mma_tf32(s[nt], qa[kk], b0, b1);
            }
        }

        // ---- online softmax ----
        float cr = -1e30f, c8 = -1e30f;
#pragma unroll
        for (int nt = 0; nt < 8; nt++) {
            cr = fmaxf(cr, fmaxf(s[nt][0], s[nt][1]));
            c8 = fmaxf(c8, fmaxf(s[nt][2], s[nt][3]));
        }
        cr = fmaxf(cr, __shfl_xor_sync(0xffffffffu, cr, 1));
        cr = fmaxf(cr, __shfl_xor_sync(0xffffffffu, cr, 2));
        c8 = fmaxf(c8, __shfl_xor_sync(0xffffffffu, c8, 1));
        c8 = fmaxf(c8, __shfl_xor_sync(0xffffffffu, c8, 2));
        float mn_r = fmaxf(m_r, cr * scale);
        float mn_8 = fmaxf(m_8, c8 * scale);
        float alpha_r = __expf(m_r - mn_r);
        float alpha_8 = __expf(m_8 - mn_8);
        m_r = mn_r; m_8 = mn_8;

        float sum_r = 0.f, sum_8 = 0.f;
#pragma unroll
        for (int nt = 0; nt < 8; nt++) {
            float p0 = __expf(s[nt][0] * scale - m_r);
            float p1 = __expf(s[nt][1] * scale - m_r);
            float p2 = __expf(s[nt][2] * scale - m_8);
            float p3 = __expf(s[nt][3] * scale - m_8);
            sum_r += p0 + p1; sum_8 += p2 + p3;
            *reinterpret_cast<float2*>(Ps + prow * 68 + nt * 8 + 2 * c) =
                make_float2(to_tf32(p0), to_tf32(p1));
            *reinterpret_cast<float2*>(Ps + (prow + 8) * 68 + nt * 8 + 2 * c) =
                make_float2(to_tf32(p2), to_tf32(p3));
            o[nt][0] *= alpha_r; o[nt][1] *= alpha_r;
            o[nt][2] *= alpha_8; o[nt][3] *= alpha_8;
        }
        sum_r += __shfl_xor_sync(0xffffffffu, sum_r, 1);
        sum_r += __shfl_xor_sync(0xffffffffu, sum_r, 2);
        sum_8 += __shfl_xor_sync(0xffffffffu, sum_8, 1);
        sum_8 += __shfl_xor_sync(0xffffffffu, sum_8, 2);
        l_r = l_r * alpha_r + sum_r;
        l_8 = l_8 * alpha_8 + sum_8;
        __syncthreads();

        // ---- O += P @ V (k-dim = kv, n-dim = d) ----
#pragma unroll
        for (int kk = 0; kk < 8; kk++) {
            unsigned pa[4];
            pa[0] = Psu[prow * 68 + kk * 8 + c];
            pa[1] = Psu[(prow + 8) * 68 + kk * 8 + c];
            pa[2] = Psu[prow * 68 + kk * 8 + c + 4];
            pa[3] = Psu[(prow + 8) * 68 + kk * 8 + c + 4];
#pragma unroll
            for (int nt = 0; nt < 8; nt++) {
                unsigned b0 = Vsu[(kk * 8 + c) * 68 + nt * 8 + g];
                unsigned b1 = Vsu[(kk * 8 + c + 4) * 68 + nt * 8 + g];
                mma_tf32(o[nt], pa, b0, b1);
            }
        }
        __syncthreads();
    }

    // ---- normalize and write in [B, LQ, H*DK] concat layout ----
    float inv_r = 1.f / l_r, inv_8 = 1.f / l_8;
    int qg = q0 + w * 16 + g;
    float* Obase = AO + ((size_t)(b * LQ_ + qg)) * DMODEL + h * DK_;
#pragma unroll
    for (int nt = 0; nt < 8; nt++) {
        *reinterpret_cast<float2*>(Obase + nt * 8 + 2 * c) =
            make_float2(o[nt][0] * inv_r, o[nt][1] * inv_r);
        *reinterpret_cast<float2*>(Obase + (size_t)8 * DMODEL + nt * 8 + 2 * c) =
            make_float2(o[nt][2] * inv_8, o[nt][3] * inv_8);
    }
}

// ---------------- launch ----------------
extern "C" void kernel_launch(void* const* d_in, const int* in_sizes, int n_in,
                              void* d_out, int out_size)
{
    (void)in_sizes; (void)n_in; (void)out_size;
    const float* q  = (const float*)d_in[0];
    const float* k  = (const float*)d_in[1];
    const float* v  = (const float*)d_in[2];
    const float* Wq = (const float*)d_in[3];
    const float* bq = (const float*)d_in[4];
    const float* Wk = (const float*)d_in[5];
    const float* bk = (const float*)d_in[6];
    const float* Wv = (const float*)d_in[7];
    const float* bv = (const float*)d_in[8];
    const float* Wo = (const float*)d_in[9];
    const float* bo = (const float*)d_in[10];
    float* out = (float*)d_out;

    float *Qp, *Kp, *Vp, *AO;
    cudaGetSymbolAddress((void**)&Qp, g_Qp);
    cudaGetSymbolAddress((void**)&Kp, g_Kp);
    cudaGetSymbolAddress((void**)&Vp, g_Vp);
    cudaGetSymbolAddress((void**)&AO, g_AO);

    cudaFuncSetAttribute(flash_attn_tf32,
                         cudaFuncAttributeMaxDynamicSharedMemorySize, 64 * 1024);

    // projections
    gemm_bias_tf32<<<dim3(DMODEL / 128, (B_SZ * LQ_) / 128), 256>>>(
        q, Wq, bq, Qp, B_SZ * LQ_, DMODEL, DMODEL);
    gemm_bias_tf32<<<dim3(DMODEL / 128, (B_SZ * LKV_) / 128), 256>>>(
        k, Wk, bk, Kp, B_SZ * LKV_, DMODEL, IMGM);
    gemm_bias_tf32<<<dim3(DMODEL / 128, (B_SZ * LKV_) / 128), 256>>>(
        v, Wv, bv, Vp, B_SZ * LKV_, DMODEL, IMGM);

    // attention (writes directly in concat layout)
    flash_attn_tf32<<<dim3(LQ_ / 64, HEADS_, B_SZ), 128, 3 * 64 * 68 * 4>>>(
        Qp, Kp, Vp, AO);

    // output projection
    gemm_bias_tf32<<<dim3(DMODEL / 128, (B_SZ * LQ_) / 128), 256>>>(
        AO, Wo, bo, out, B_SZ * LQ_, DMODEL, DMODEL);
}

// round 2
// speedup vs baseline: 1.2969x; 1.2969x over previous
#include <cuda_runtime.h>
#include <cstdint>
#include <cstddef>

#define B_SZ   8
#define LQ_    2048
#define LKV_   1024
#define DMODEL 1024
#define IMGM   512
#define HEADS_ 16
#define DK_    64

// ---------------- scratch (no allocations allowed) ----------------
__device__ float g_qr[(size_t)B_SZ * LQ_  * DMODEL];   // 64 MB rounded q
__device__ float g_kr[(size_t)B_SZ * LKV_ * IMGM];     // 16 MB rounded k
__device__ float g_vr[(size_t)B_SZ * LKV_ * IMGM];     // 16 MB rounded v
__device__ float g_Wqr[(size_t)DMODEL * DMODEL];       // 4 MB
__device__ float g_Wkr[(size_t)IMGM * DMODEL];         // 2 MB
__device__ float g_Wvr[(size_t)IMGM * DMODEL];         // 2 MB
__device__ float g_Wor[(size_t)DMODEL * DMODEL];       // 4 MB
__device__ float g_Qp[(size_t)B_SZ * LQ_  * DMODEL];   // 64 MB
__device__ float g_Kp[(size_t)B_SZ * LKV_ * DMODEL];   // 32 MB
__device__ float g_Vp[(size_t)B_SZ * LKV_ * DMODEL];   // 32 MB
__device__ float g_AO[(size_t)B_SZ * LQ_  * DMODEL];   // 64 MB

// ---------------- helpers ----------------
__device__ __forceinline__ float to_tf32(float x) {
    float r;
    asm("cvt.rna.tf32.f32 %0, %1;" : "=f"(r) : "f"(x));
    return r;
}

__device__ __forceinline__ void mma_tf32(float d[4], const unsigned a[4],
                                         unsigned b0, unsigned b1) {
    asm volatile(
        "mma.sync.aligned.m16n8k8.row.col.f32.tf32.tf32.f32 "
        "{%0,%1,%2,%3}, {%4,%5,%6,%7}, {%8,%9}, {%0,%1,%2,%3};"
        : "+f"(d[0]), "+f"(d[1]), "+f"(d[2]), "+f"(d[3])
        : "r"(a[0]), "r"(a[1]), "r"(a[2]), "r"(a[3]), "r"(b0), "r"(b1));
}

__device__ __forceinline__ void cp_async16(void* smem_dst, const void* gmem_src) {
    unsigned s = (unsigned)__cvta_generic_to_shared(smem_dst);
    asm volatile("cp.async.cg.shared.global [%0], [%1], 16;\n" :: "r"(s), "l"(gmem_src));
}
__device__ __forceinline__ void cp_commit() {
    asm volatile("cp.async.commit_group;\n");
}
template <int N> __device__ __forceinline__ void cp_wait() {
    asm volatile("cp.async.wait_group %0;\n" :: "n"(N));
}

// ---------------- elementwise tf32 rounding ----------------
__global__ __launch_bounds__(256) void round_tf32_kernel(
    const float* __restrict__ in, float* __restrict__ out, int n4)
{
    int i = blockIdx.x * blockDim.x + threadIdx.x;
    if (i < n4) {
        float4 v = reinterpret_cast<const float4*>(in)[i];
        v.x = to_tf32(v.x); v.y = to_tf32(v.y);
        v.z = to_tf32(v.z); v.w = to_tf32(v.w);
        reinterpret_cast<float4*>(out)[i] = v;
    }
}

// ---------------- GEMM: C[M,N] = A[M,K] @ B[K,N] + bias ----------------
// A, B pre-rounded to tf32. 128x128 tile, K-tile 32, cp.async double buffer.
// 256 threads = 8 warps (4 along M x 2 along N); warp tile 32x64.
#define AS_STRIDE 36
#define BS_STRIDE 136
#define AS_TILE (128 * AS_STRIDE)
#define BS_TILE (32 * BS_STRIDE)
#define GEMM_SMEM ((2 * AS_TILE + 2 * BS_TILE) * 4)

template <bool ROUND_OUT>
__global__ __launch_bounds__(256, 2) void gemm_bias_cp(
    const float* __restrict__ A, const float* __restrict__ Bm,
    const float* __restrict__ bias, float* __restrict__ C,
    int M, int N, int K)
{
    extern __shared__ float sm[];
    float* As = sm;                    // 2 stages
    float* Bs = sm + 2 * AS_TILE;      // 2 stages

    const int tid  = threadIdx.x;
    const int warp = tid >> 5, lane = tid & 31;
    const int wm = warp & 3, wn = warp >> 2;
    const int g = lane >> 2, c = lane & 3;
    const int m0 = blockIdx.y * 128, n0 = blockIdx.x * 128;

    const int arow = tid >> 3, acol = (tid & 7) * 4;
    const int brow = tid >> 5, bcol = (tid & 31) * 4;

    auto load_stage = [&](int s, int k0) {
        float* as = As + s * AS_TILE;
        float* bs = Bs + s * BS_TILE;
#pragma unroll
        for (int p = 0; p < 4; p++) {
            int r = arow + p * 32;
            cp_async16(as + r * AS_STRIDE + acol,
                       A + (size_t)(m0 + r) * K + k0 + acol);
        }
#pragma unroll
        for (int p = 0; p < 4; p++) {
            int r = brow + p * 8;
            cp_async16(bs + r * BS_STRIDE + bcol,
                       Bm + (size_t)(k0 + r) * N + n0 + bcol);
        }
    };

    float acc[2][8][4];
#pragma unroll
    for (int i = 0; i < 2; i++)
#pragma unroll
        for (int j = 0; j < 8; j++)
#pragma unroll
            for (int t = 0; t < 4; t++) acc[i][j][t] = 0.f;

    const int KT = K >> 5;
    load_stage(0, 0);  cp_commit();
    load_stage(1, 32); cp_commit();

    for (int kt = 0; kt < KT; kt++) {
        cp_wait<1>();
        __syncthreads();
        const unsigned* Asu = reinterpret_cast<const unsigned*>(As + (kt & 1) * AS_TILE);
        const unsigned* Bsu = reinterpret_cast<const unsigned*>(Bs + (kt & 1) * BS_TILE);

#pragma unroll
        for (int kk = 0; kk < 32; kk += 8) {
            unsigned af[2][4];
#pragma unroll
            for (int mt = 0; mt < 2; mt++) {
                int r = wm * 32 + mt * 16 + g;
                af[mt][0] = Asu[r * AS_STRIDE + kk + c];
                af[mt][1] = Asu[(r + 8) * AS_STRIDE + kk + c];
                af[mt][2] = Asu[r * AS_STRIDE + kk + c + 4];
                af[mt][3] = Asu[(r + 8) * AS_STRIDE + kk + c + 4];
            }
#pragma unroll
            for (int nt = 0; nt < 8; nt++) {
                int ncol = wn * 64 + nt * 8 + g;
                unsigned b0 = Bsu[(kk + c) * BS_STRIDE + ncol];
                unsigned b1 = Bsu[(kk + c + 4) * BS_STRIDE + ncol];
                mma_tf32(acc[0][nt], af[0], b0, b1);
                mma_tf32(acc[1][nt], af[1], b0, b1);
            }
        }
        __syncthreads();
        if (kt + 2 < KT) load_stage(kt & 1, (kt + 2) * 32);
        cp_commit();
    }

#pragma unroll
    for (int mt = 0; mt < 2; mt++) {
        int row = m0 + wm * 32 + mt * 16 + g;
#pragma unroll
        for (int nt = 0; nt < 8; nt++) {
            int col = n0 + wn * 64 + nt * 8 + 2 * c;
            float2 bv = *reinterpret_cast<const float2*>(bias + col);
            float2 r0 = make_float2(acc[mt][nt][0] + bv.x, acc[mt][nt][1] + bv.y);
            float2 r1 = make_float2(acc[mt][nt][2] + bv.x, acc[mt][nt][3] + bv.y);
            if (ROUND_OUT) {
                r0.x = to_tf32(r0.x); r0.y = to_tf32(r0.y);
                r1.x = to_tf32(r1.x); r1.y = to_tf32(r1.y);
            }
            *reinterpret_cast<float2*>(C + (size_t)row * N + col)       = r0;
            *reinterpret_cast<float2*>(C + (size_t)(row + 8) * N + col) = r1;
        }
    }
}

// ---------------- flash attention v2 ----------------
// One block = one (b, h, 128-row Q tile). 256 threads = 8 warps; warp w owns
// Q rows [w*16, w*16+16). KV tiles of 64 rows double-buffered via cp.async.
// Inputs Qp/Kp/Vp are pre-rounded tf32. Output AO written tf32-rounded.
#define KV_STRIDE 68
#define KV_TILE   (64 * KV_STRIDE)
#define PS_STRIDE 68
#define FLASH_SMEM ((4 * KV_TILE + 128 * PS_STRIDE) * 4)

__global__ __launch_bounds__(256, 2) void flash_attn_tf32(
    const float* __restrict__ Qp, const float* __restrict__ Kp,
    const float* __restrict__ Vp, float* __restrict__ AO)
{
    extern __shared__ float sm[];
    float* Kst = sm;                 // 2 stages of 64x68
    float* Vst = sm + 2 * KV_TILE;   // 2 stages of 64x68
    float* Ps  = sm + 4 * KV_TILE;   // 128x68 (Q staging, then P)
    unsigned* Psu = reinterpret_cast<unsigned*>(Ps);

    const int tid = threadIdx.x;
    const int w = tid >> 5, lane = tid & 31;
    const int g = lane >> 2, c = lane & 3;
    const int qt = blockIdx.x, h = blockIdx.y, b = blockIdx.z;
    const int q0 = qt * 128;

    const float* Qbase = Qp + ((size_t)(b * LQ_ + q0)) * DMODEL + h * DK_;
    const float* Kbase = Kp + ((size_t)b * LKV_) * DMODEL + h * DK_;
    const float* Vbase = Vp + ((size_t)b * LKV_) * DMODEL + h * DK_;

    auto load_kv = [&](int s, int kv0) {
        float* ks = Kst + s * KV_TILE;
        float* vs = Vst + s * KV_TILE;
#pragma unroll
        for (int p = 0; p < 4; p++) {
            int idx = tid + p * 256;          // 0..1023
            int row = idx >> 4;
            int col = (idx & 15) * 4;
            cp_async16(ks + row * KV_STRIDE + col,
                       Kbase + (size_t)(kv0 + row) * DMODEL + col);
        }
#pragma unroll
        for (int p = 0; p < 4; p++) {
            int idx = tid + p * 256;
            int row = idx >> 4;
            int col = (idx & 15) * 4;
            cp_async16(vs + row * KV_STRIDE + col,
                       Vbase + (size_t)(kv0 + row) * DMODEL + col);
        }
    };

    // ---- stage Q tile (128x64) into Ps via cp.async ----
#pragma unroll
    for (int p = 0; p < 8; p++) {
        int idx = tid + p * 256;              // 0..2047
        int row = idx >> 4;
        int col = (idx & 15) * 4;
        cp_async16(Ps + row * PS_STRIDE + col,
                   Qbase + (size_t)row * DMODEL + col);
    }
    cp_commit();                 // G0 = Q
    load_kv(0, 0);  cp_commit(); // G1 = KV tile 0
    load_kv(1, 64); cp_commit(); // G2 = KV tile 1

    cp_wait<2>();                // Q ready
    __syncthreads();

    unsigned qa[8][4];
    const int prow = w * 16 + g;
#pragma unroll
    for (int kk = 0; kk < 8; kk++) {
        qa[kk][0] = Psu[prow * PS_STRIDE + kk * 8 + c];
        qa[kk][1] = Psu[(prow + 8) * PS_STRIDE + kk * 8 + c];
        qa[kk][2] = Psu[prow * PS_STRIDE + kk * 8 + c + 4];
        qa[kk][3] = Psu[(prow + 8) * PS_STRIDE + kk * 8 + c + 4];
    }
    // Ps rows are per-warp private from here on; no block sync needed.

    float o[8][4];
#pragma unroll
    for (int i = 0; i < 8; i++)
#pragma unroll
        for (int j = 0; j < 4; j++) o[i][j] = 0.f;

    float m_r = -1e30f, m_8 = -1e30f, l_r = 0.f, l_8 = 0.f;
    const float scale = 0.125f;  // 1/sqrt(64)

    for (int t = 0; t < LKV_ / 64; t++) {
        cp_wait<1>();            // KV tile t landed
        __syncthreads();
        const unsigned* Ksu = reinterpret_cast<const unsigned*>(Kst + (t & 1) * KV_TILE);
        const unsigned* Vsu = reinterpret_cast<const unsigned*>(Vst + (t & 1) * KV_TILE);

        // ---- S = Q @ K^T ----
        float s[8][4];
#pragma unroll
        for (int i = 0; i < 8; i++)
#pragma unroll
            for (int j = 0; j < 4; j++) s[i][j] = 0.f;
#pragma unroll
        for (int nt = 0; nt < 8; nt++) {
#pragma unroll
            for (int kk = 0; kk < 8; kk++) {
                unsigned b0 = Ksu[(nt * 8 + g) * KV_STRIDE + kk * 8 + c];
                unsigned b1 = Ksu[(nt * 8 + g) * KV_STRIDE + kk * 8 + c + 4];
                mma_tf32(s[nt], qa[kk], b0, b1);
            }
        }

        // ---- online softmax ----
        float cr = -1e30f, c8 = -1e30f;
#pragma unroll
        for (int nt = 0; nt < 8; nt++) {
            cr = fmaxf(cr, fmaxf(s[nt][0], s[nt][1]));
            c8 = fmaxf(c8, fmaxf(s[nt][2], s[nt][3]));
        }
        cr = fmaxf(cr, __shfl_xor_sync(0xffffffffu, cr, 1));
        cr = fmaxf(cr, __shfl_xor_sync(0xffffffffu, cr, 2));
        c8 = fmaxf(c8, __shfl_xor_sync(0xffffffffu, c8, 1));
        c8 = fmaxf(c8, __shfl_xor_sync(0xffffffffu, c8, 2));
        float mn_r = fmaxf(m_r, cr * scale);
        float mn_8 = fmaxf(m_8, c8 * scale);
        float alpha_r = __expf(m_r - mn_r);
        float alpha_8 = __expf(m_8 - mn_8);
        m_r = mn_r; m_8 = mn_8;

        float sum_r = 0.f, sum_8 = 0.f;
#pragma unroll
        for (int nt = 0; nt < 8; nt++) {
            float p0 = __expf(s[nt][0] * scale - m_r);
            float p1 = __expf(s[nt][1] * scale - m_r);
            float p2 = __expf(s[nt][2] * scale - m_8);
            float p3 = __expf(s[nt][3] * scale - m_8);
            sum_r += p0 + p1; sum_8 += p2 + p3;
            *reinterpret_cast<float2*>(Ps + prow * PS_STRIDE + nt * 8 + 2 * c) =
                make_float2(to_tf32(p0), to_tf32(p1));
            *reinterpret_cast<float2*>(Ps + (prow + 8) * PS_STRIDE + nt * 8 + 2 * c) =
                make_float2(to_tf32(p2), to_tf32(p3));
            o[nt][0] *= alpha_r; o[nt][1] *= alpha_r;
            o[nt][2] *= alpha_8; o[nt][3] *= alpha_8;
        }
        sum_r += __shfl_xor_sync(0xffffffffu, sum_r, 1);
        sum_r += __shfl_xor_sync(0xffffffffu, sum_r, 2);
        sum_8 += __shfl_xor_sync(0xffffffffu, sum_8, 1);
        sum_8 += __shfl_xor_sync(0xffffffffu, sum_8, 2);
        l_r = l_r * alpha_r + sum_r;
        l_8 = l_8 * alpha_8 + sum_8;
        __syncwarp();

        // ---- O += P @ V ----
#pragma unroll
        for (int kk = 0; kk < 8; kk++) {
            unsigned pa[4];
            pa[0] = Psu[prow * PS_STRIDE + kk * 8 + c];
            pa[1] = Psu[(prow + 8) * PS_STRIDE + kk * 8 + c];
            pa[2] = Psu[prow * PS_STRIDE + kk * 8 + c + 4];
            pa[3] = Psu[(prow + 8) * PS_STRIDE + kk * 8 + c + 4];
#pragma unroll
            for (int nt = 0; nt < 8; nt++) {
                unsigned b0 = Vsu[(kk * 8 + c) * KV_STRIDE + nt * 8 + g];
                unsigned b1 = Vsu[(kk * 8 + c + 4) * KV_STRIDE + nt * 8 + g];
                mma_tf32(o[nt], pa, b0, b1);
            }
        }
        __syncthreads();   // all warps done reading stage (t&1) before refill
        if (t + 2 < LKV_ / 64) load_kv(t & 1, (t + 2) * 64);
        cp_commit();
    }

    // ---- normalize, round to tf32 (feeds O-proj), write concat layout ----
    float inv_r = 1.f / l_r, inv_8 = 1.f / l_8;
    int qg = q0 + w * 16 + g;
    float* Obase = AO + ((size_t)(b * LQ_ + qg)) * DMODEL + h * DK_;
#pragma unroll
    for (int nt = 0; nt < 8; nt++) {
        *reinterpret_cast<float2*>(Obase + nt * 8 + 2 * c) =
            make_float2(to_tf32(o[nt][0] * inv_r), to_tf32(o[nt][1] * inv_r));
        *reinterpret_cast<float2*>(Obase + (size_t)8 * DMODEL + nt * 8 + 2 * c) =
            make_float2(to_tf32(o[nt][2] * inv_8), to_tf32(o[nt][3] * inv_8));
    }
}

// ---------------- launch ----------------
extern "C" void kernel_launch(void* const* d_in, const int* in_sizes, int n_in,
                              void* d_out, int out_size)
{
    (void)in_sizes; (void)n_in; (void)out_size;
    const float* q  = (const float*)d_in[0];
    const float* k  = (const float*)d_in[1];
    const float* v  = (const float*)d_in[2];
    const float* Wq = (const float*)d_in[3];
    const float* bq = (const float*)d_in[4];
    const float* Wk = (const float*)d_in[5];
    const float* bk = (const float*)d_in[6];
    const float* Wv = (const float*)d_in[7];
    const float* bv = (const float*)d_in[8];
    const float* Wo = (const float*)d_in[9];
    const float* bo = (const float*)d_in[10];
    float* out = (float*)d_out;

    float *qr, *kr, *vr, *Wqr, *Wkr, *Wvr, *Wor, *Qp, *Kp, *Vp, *AO;
    cudaGetSymbolAddress((void**)&qr,  g_qr);
    cudaGetSymbolAddress((void**)&kr,  g_kr);
    cudaGetSymbolAddress((void**)&vr,  g_vr);
    cudaGetSymbolAddress((void**)&Wqr, g_Wqr);
    cudaGetSymbolAddress((void**)&Wkr, g_Wkr);
    cudaGetSymbolAddress((void**)&Wvr, g_Wvr);
    cudaGetSymbolAddress((void**)&Wor, g_Wor);
    cudaGetSymbolAddress((void**)&Qp,  g_Qp);
    cudaGetSymbolAddress((void**)&Kp,  g_Kp);
    cudaGetSymbolAddress((void**)&Vp,  g_Vp);
    cudaGetSymbolAddress((void**)&AO,  g_AO);

    cudaFuncSetAttribute(gemm_bias_cp<true>,
                         cudaFuncAttributeMaxDynamicSharedMemorySize, GEMM_SMEM);
    cudaFuncSetAttribute(gemm_bias_cp<false>,
                         cudaFuncAttributeMaxDynamicSharedMemorySize, GEMM_SMEM);
    cudaFuncSetAttribute(flash_attn_tf32,
                         cudaFuncAttributeMaxDynamicSharedMemorySize, FLASH_SMEM);

    // ---- tf32 pre-rounding of all GEMM operands ----
    auto round_launch = [&](const float* src, float* dst, size_t n) {
        int n4 = (int)(n / 4);
        round_tf32_kernel<<<(n4 + 255) / 256, 256>>>(src, dst, n4);
    };
    round_launch(q,  qr,  (size_t)B_SZ * LQ_  * DMODEL);
    round_launch(k,  kr,  (size_t)B_SZ * LKV_ * IMGM);
    round_launch(v,  vr,  (size_t)B_SZ * LKV_ * IMGM);
    round_launch(Wq, Wqr, (size_t)DMODEL * DMODEL);
    round_launch(Wk, Wkr, (size_t)IMGM * DMODEL);
    round_launch(Wv, Wvr, (size_t)IMGM * DMODEL);
    round_launch(Wo, Wor, (size_t)DMODEL * DMODEL);

    // ---- projections (outputs rounded to tf32 for attention) ----
    gemm_bias_cp<true><<<dim3(DMODEL / 128, (B_SZ * LQ_) / 128), 256, GEMM_SMEM>>>(
        qr, Wqr, bq, Qp, B_SZ * LQ_, DMODEL, DMODEL);
    gemm_bias_cp<true><<<dim3(DMODEL / 128, (B_SZ * LKV_) / 128), 256, GEMM_SMEM>>>(
        kr, Wkr, bk, Kp, B_SZ * LKV_, DMODEL, IMGM);
    gemm_bias_cp<true><<<dim3(DMODEL / 128, (B_SZ * LKV_) / 128), 256, GEMM_SMEM>>>(
        vr, Wvr, bv, Vp, B_SZ * LKV_, DMODEL, IMGM);

    // ---- attention (writes tf32-rounded concat layout) ----
    flash_attn_tf32<<<dim3(LQ_ / 128, HEADS_, B_SZ), 256, FLASH_SMEM>>>(
        Qp, Kp, Vp, AO);

    // ---- output projection (fp32 out) ----
    gemm_bias_cp<false><<<dim3(DMODEL / 128, (B_SZ * LQ_) / 128), 256, GEMM_SMEM>>>(
        AO, Wor, bo, out, B_SZ * LQ_, DMODEL, DMODEL);
}

// round 4
// speedup vs baseline: 2.5749x; 1.9855x over previous
#include <cuda_runtime.h>
#include <cuda_fp16.h>
#include <cstdint>
#include <cstddef>

#define B_SZ   8
#define LQ_    2048
#define LKV_   1024
#define DMODEL 1024
#define IMGM   512
#define HEADS_ 16
#define DK_    64

// ---------------- scratch (no allocations allowed) ----------------
__device__ __half g_qr[(size_t)B_SZ * LQ_  * DMODEL];
__device__ __half g_kr[(size_t)B_SZ * LKV_ * IMGM];
__device__ __half g_vr[(size_t)B_SZ * LKV_ * IMGM];
__device__ __half g_Wqt[(size_t)DMODEL * DMODEL];   // W^T as half
__device__ __half g_Wkt[(size_t)DMODEL * IMGM];
__device__ __half g_Wvt[(size_t)DMODEL * IMGM];
__device__ __half g_Wot[(size_t)DMODEL * DMODEL];
__device__ __half g_Qp[(size_t)B_SZ * LQ_  * DMODEL];
__device__ __half g_Kp[(size_t)B_SZ * LKV_ * DMODEL];
__device__ __half g_Vp[(size_t)B_SZ * LKV_ * DMODEL];
__device__ __half g_AO[(size_t)B_SZ * LQ_  * DMODEL];

// ---------------- helpers ----------------
__device__ __forceinline__ void mma_f16(float d[4], const uint32_t a[4],
                                        uint32_t b0, uint32_t b1) {
    asm volatile(
        "mma.sync.aligned.m16n8k16.row.col.f32.f16.f16.f32 "
        "{%0,%1,%2,%3}, {%4,%5,%6,%7}, {%8,%9}, {%0,%1,%2,%3};"
        : "+f"(d[0]), "+f"(d[1]), "+f"(d[2]), "+f"(d[3])
        : "r"(a[0]), "r"(a[1]), "r"(a[2]), "r"(a[3]), "r"(b0), "r"(b1));
}

__device__ __forceinline__ void ldm4(uint32_t& r0, uint32_t& r1, uint32_t& r2,
                                     uint32_t& r3, uint32_t addr) {
    asm volatile("ldmatrix.sync.aligned.m8n8.x4.shared.b16 {%0,%1,%2,%3}, [%4];"
                 : "=r"(r0), "=r"(r1), "=r"(r2), "=r"(r3) : "r"(addr));
}
__device__ __forceinline__ void ldm4t(uint32_t& r0, uint32_t& r1, uint32_t& r2,
                                      uint32_t& r3, uint32_t addr) {
    asm volatile("ldmatrix.sync.aligned.m8n8.x4.trans.shared.b16 {%0,%1,%2,%3}, [%4];"
                 : "=r"(r0), "=r"(r1), "=r"(r2), "=r"(r3) : "r"(addr));
}

__device__ __forceinline__ void cp_async16(void* smem_dst, const void* gmem_src) {
    unsigned s = (unsigned)__cvta_generic_to_shared(smem_dst);
    asm volatile("cp.async.cg.shared.global [%0], [%1], 16;\n" :: "r"(s), "l"(gmem_src));
}
__device__ __forceinline__ void cp_commit() {
    asm volatile("cp.async.commit_group;\n");
}
template <int N> __device__ __forceinline__ void cp_wait() {
    asm volatile("cp.async.wait_group %0;\n" :: "n"(N));
}

__device__ __forceinline__ uint32_t packh2(float a, float b) {
    __half2 h = __floats2half2_rn(a, b);
    return *reinterpret_cast<uint32_t*>(&h);
}

// ---------------- elementwise round to half ----------------
__global__ __launch_bounds__(256) void round_half_kernel(
    const float* __restrict__ in, __half* __restrict__ out, int n4)
{
    int i = blockIdx.x * blockDim.x + threadIdx.x;
    if (i < n4) {
        float4 v = reinterpret_cast<const float4*>(in)[i];
        __half2 lo = __floats2half2_rn(v.x, v.y);
        __half2 hi = __floats2half2_rn(v.z, v.w);
        reinterpret_cast<__half2*>(out)[2 * i]     = lo;
        reinterpret_cast<__half2*>(out)[2 * i + 1] = hi;
    }
}

// ---------------- transpose + round: in[K][N] f32 -> out[N][K] half ----------------
__global__ __launch_bounds__(256) void transpose_half_kernel(
    const float* __restrict__ in, __half* __restrict__ out, int K, int N)
{
    __shared__ float tile[32][33];
    int k0 = blockIdx.y * 32, n0 = blockIdx.x * 32;
    int tx = threadIdx.x, ty = threadIdx.y;
#pragma unroll
    for (int i = ty; i < 32; i += 8)
        tile[i][tx] = in[(size_t)(k0 + i) * N + n0 + tx];
    __syncthreads();
#pragma unroll
    for (int i = ty; i < 32; i += 8)
        out[(size_t)(n0 + i) * K + k0 + tx] = __float2half_rn(tile[tx][i]);
}

// ---------------- fp16 GEMM: C[M,N] = A[M,K] @ Bt[N,K]^T + bias ----------------
// A, Bt row-major half. 128x128 tile, BK=32 halves, 3-stage cp.async.
// 8 warps: 4 along M x 2 along N; warp tile 32x64.
#define GBM 128
#define GBN 128
#define GBK 32
#define GSTG 3
#define ASTR 40                       // halves per smem row (32 + 8 pad)
#define ATILE (GBM * ASTR)            // halves per stage (A or B)
#define GSMEM (2 * GSTG * ATILE * 2)  // bytes = 61440

template <bool HALF_OUT>
__global__ __launch_bounds__(256, 2) void gemm_f16(
    const __half* __restrict__ A, const __half* __restrict__ Bt,
    const float* __restrict__ bias, void* __restrict__ Cp,
    int M, int N, int K)
{
    extern __shared__ __half smh[];
    __half* sA = smh;
    __half* sB = smh + GSTG * ATILE;
    const uint32_t sAb = (uint32_t)__cvta_generic_to_shared(sA);
    const uint32_t sBb = (uint32_t)__cvta_generic_to_shared(sB);

    const int tid = threadIdx.x;
    const int warp = tid >> 5, lane = tid & 31;
    const int wm = warp & 3, wn = warp >> 2;
    const int g = lane >> 2, c = lane & 3;
    const int m0 = blockIdx.y * GBM, n0 = blockIdx.x * GBN;

    auto load_stage = [&](int t, int s) {
#pragma unroll
        for (int p = 0; p < 2; p++) {
            int idx = tid + p * 256;
            int row = idx >> 2, ch = idx & 3;
            cp_async16(sA + s * ATILE + row * ASTR + ch * 8,
                       A + (size_t)(m0 + row) * K + t * GBK + ch * 8);
        }
#pragma unroll
        for (int p = 0; p < 2; p++) {
            int idx = tid + p * 256;
            int row = idx >> 2, ch = idx & 3;
            cp_async16(sB + s * ATILE + row * ASTR + ch * 8,
                       Bt + (size_t)(n0 + row) * K + t * GBK + ch * 8);
        }
    };

    float acc[2][8][4];
#pragma unroll
    for (int i = 0; i < 2; i++)
#pragma unroll
        for (int j = 0; j < 8; j++)
#pragma unroll
            for (int t = 0; t < 4; t++) acc[i][j][t] = 0.f;

    const int T = K / GBK;
    for (int i = 0; i < GSTG; i++) { load_stage(i, i); cp_commit(); }

    int s = 0;
    for (int t = 0; t < T; t++) {
        cp_wait<GSTG - 1>();
        __syncthreads();
        const uint32_t ab = sAb + s * ATILE * 2;
        const uint32_t bb = sBb + s * ATILE * 2;

#pragma unroll
        for (int kk = 0; kk < 2; kk++) {
            uint32_t af[2][4];
#pragma unroll
            for (int mt = 0; mt < 2; mt++) {
                int lrow = wm * 32 + mt * 16 + (lane & 15);
                int lcol = kk * 16 + (lane >> 4) * 8;
                ldm4(af[mt][0], af[mt][1], af[mt][2], af[mt][3],
                     ab + (lrow * ASTR + lcol) * 2);
            }
            uint32_t bf[8][2];
#pragma unroll
            for (int ng = 0; ng < 4; ng++) {
                int nrow = wn * 64 + ng * 16 + (lane & 7) + ((lane & 16) ? 8 : 0);
                int ncol = kk * 16 + ((lane >> 3) & 1) * 8;
                uint32_t r0, r1, r2, r3;
                ldm4(r0, r1, r2, r3, bb + (nrow * ASTR + ncol) * 2);
                bf[2 * ng][0] = r0;     bf[2 * ng][1] = r1;
                bf[2 * ng + 1][0] = r2; bf[2 * ng + 1][1] = r3;
            }
#pragma unroll
            for (int mt = 0; mt < 2; mt++)
#pragma unroll
                for (int nt = 0; nt < 8; nt++)
                    mma_f16(acc[mt][nt], af[mt], bf[nt][0], bf[nt][1]);
        }
        __syncthreads();
        if (t + GSTG < T) load_stage(t + GSTG, s);
        cp_commit();
        s = (s + 1 == GSTG) ? 0 : s + 1;
    }

    // epilogue
#pragma unroll
    for (int mt = 0; mt < 2; mt++) {
        int row = m0 + wm * 32 + mt * 16 + g;
#pragma unroll
        for (int nt = 0; nt < 8; nt++) {
            int col = n0 + wn * 64 + nt * 8 + 2 * c;
            float2 bv = *reinterpret_cast<const float2*>(bias + col);
            float v0 = acc[mt][nt][0] + bv.x, v1 = acc[mt][nt][1] + bv.y;
            float v2 = acc[mt][nt][2] + bv.x, v3 = acc[mt][nt][3] + bv.y;
            if (HALF_OUT) {
                __half* C = (__half*)Cp;
                *reinterpret_cast<__half2*>(C + (size_t)row * N + col) =
                    __floats2half2_rn(v0, v1);
                *reinterpret_cast<__half2*>(C + (size_t)(row + 8) * N + col) =
                    __floats2half2_rn(v2, v3);
            } else {
                float* C = (float*)Cp;
                *reinterpret_cast<float2*>(C + (size_t)row * N + col) =
                    make_float2(v0, v1);
                *reinterpret_cast<float2*>(C + (size_t)(row + 8) * N + col) =
                    make_float2(v2, v3);
            }
        }
    }
}

// ---------------- fp16 flash attention ----------------
// Block = (b, h, 128 Q rows). 256 threads = 8 warps; warp w owns Q rows
// [w*16, w*16+16). KV tiles of 64 double-buffered. P stays in registers.
#define FSTR 72                       // halves per smem row (64 + 8 pad)
#define KTILE (64 * FSTR)             // halves per K or V stage
#define FLASH_SMEM ((4 * KTILE + 128 * FSTR) * 2)  // 55296 B

__global__ __launch_bounds__(256, 2) void flash_f16(
    const __half* __restrict__ Qp, const __half* __restrict__ Kp,
    const __half* __restrict__ Vp, __half* __restrict__ AO)
{
    extern __shared__ __half smh[];
    __half* sK = smh;
    __half* sV = smh + 2 * KTILE;
    __half* sQ = smh + 4 * KTILE;
    const uint32_t sKb = (uint32_t)__cvta_generic_to_shared(sK);
    const uint32_t sVb = (uint32_t)__cvta_generic_to_shared(sV);
    const uint32_t sQb = (uint32_t)__cvta_generic_to_shared(sQ);

    const int tid = threadIdx.x;
    const int w = tid >> 5, lane = tid & 31;
    const int g = lane >> 2, c = lane & 3;
    const int q0 = blockIdx.x * 128, h = blockIdx.y, b = blockIdx.z;

    const __half* Qbase = Qp + ((size_t)(b * LQ_ + q0)) * DMODEL + h * DK_;
    const __half* Kbase = Kp + ((size_t)b * LKV_) * DMODEL + h * DK_;
    const __half* Vbase = Vp + ((size_t)b * LKV_) * DMODEL + h * DK_;

    auto load_kv = [&](int s, int kv0) {
#pragma unroll
        for (int p = 0; p < 2; p++) {
            int idx = tid + p * 256;
            int row = idx >> 3, ch = idx & 7;
            cp_async16(sK + s * KTILE + row * FSTR + ch * 8,
                       Kbase + (size_t)(kv0 + row) * DMODEL + ch * 8);
        }
#pragma unroll
        for (int p = 0; p < 2; p++) {
            int idx = tid + p * 256;
            int row = idx >> 3, ch = idx & 7;
            cp_async16(sV + s * KTILE + row * FSTR + ch * 8,
                       Vbase + (size_t)(kv0 + row) * DMODEL + ch * 8);
        }
    };

    // stage Q (128x64 halves)
#pragma unroll
    for (int p = 0; p < 4; p++) {
        int idx = tid + p * 256;
        int row = idx >> 3, ch = idx & 7;
        cp_async16(sQ + row * FSTR + ch * 8,
                   Qbase + (size_t)row * DMODEL + ch * 8);
    }
    cp_commit();
    load_kv(0, 0);  cp_commit();
    load_kv(1, 64); cp_commit();

    cp_wait<2>();
    __syncthreads();

    uint32_t qa[4][4];
#pragma unroll
    for (int kk = 0; kk < 4; kk++) {
        int lrow = w * 16 + (lane & 15);
        int lcol = kk * 16 + (lane >> 4) * 8;
        ldm4(qa[kk][0], qa[kk][1], qa[kk][2], qa[kk][3],
             sQb + (lrow * FSTR + lcol) * 2);
    }

    float o[8][4];
#pragma unroll
    for (int i = 0; i < 8; i++)
#pragma unroll
        for (int j = 0; j < 4; j++) o[i][j] = 0.f;

    float m_r = -1e30f, m_8 = -1e30f, l_r = 0.f, l_8 = 0.f;
    const float scale = 0.125f;  // 1/sqrt(64)

    for (int t = 0; t < LKV_ / 64; t++) {
        cp_wait<1>();
        __syncthreads();
        const uint32_t kb = sKb + (t & 1) * KTILE * 2;
        const uint32_t vbb = sVb + (t & 1) * KTILE * 2;

        // ---- S = Q @ K^T ----
        float s[8][4];
#pragma unroll
        for (int i = 0; i < 8; i++)
#pragma unroll
            for (int j = 0; j < 4; j++) s[i][j] = 0.f;
#pragma unroll
        for (int kk = 0; kk < 4; kk++) {
            uint32_t bf[8][2];
#pragma unroll
            for (int ng = 0; ng < 4; ng++) {
                int nrow = ng * 16 + (lane & 7) + ((lane & 16) ? 8 : 0);
                int ncol = kk * 16 + ((lane >> 3) & 1) * 8;
                uint32_t r0, r1, r2, r3;
                ldm4(r0, r1, r2, r3, kb + (nrow * FSTR + ncol) * 2);
                bf[2 * ng][0] = r0;     bf[2 * ng][1] = r1;
                bf[2 * ng + 1][0] = r2; bf[2 * ng + 1][1] = r3;
            }
#pragma unroll
            for (int nt = 0; nt < 8; nt++)
                mma_f16(s[nt], qa[kk], bf[nt][0], bf[nt][1]);
        }

        // ---- online softmax (rows g and g+8) ----
        float cr = -1e30f, c8 = -1e30f;
#pragma unroll
        for (int nt = 0; nt < 8; nt++) {
            cr = fmaxf(cr, fmaxf(s[nt][0], s[nt][1]));
            c8 = fmaxf(c8, fmaxf(s[nt][2], s[nt][3]));
        }
        cr = fmaxf(cr, __shfl_xor_sync(0xffffffffu, cr, 1));
        cr = fmaxf(cr, __shfl_xor_sync(0xffffffffu, cr, 2));
        c8 = fmaxf(c8, __shfl_xor_sync(0xffffffffu, c8, 1));
        c8 = fmaxf(c8, __shfl_xor_sync(0xffffffffu, c8, 2));
        float mn_r = fmaxf(m_r, cr * scale);
        float mn_8 = fmaxf(m_8, c8 * scale);
        float alpha_r = __expf(m_r - mn_r);
        float alpha_8 = __expf(m_8 - mn_8);
        m_r = mn_r; m_8 = mn_8;

        float sum_r = 0.f, sum_8 = 0.f;
#pragma unroll
        for (int nt = 0; nt < 8; nt++) {
            s[nt][0] = __expf(s[nt][0] * scale - m_r);
            s[nt][1] = __expf(s[nt][1] * scale - m_r);
            s[nt][2] = __expf(s[nt][2] * scale - m_8);
            s[nt][3] = __expf(s[nt][3] * scale - m_8);
            sum_r += s[nt][0] + s[nt][1];
            sum_8 += s[nt][2] + s[nt][3];
            o[nt][0] *= alpha_r; o[nt][1] *= alpha_r;
            o[nt][2] *= alpha_8; o[nt][3] *= alpha_8;
        }
        sum_r += __shfl_xor_sync(0xffffffffu, sum_r, 1);
        sum_r += __shfl_xor_sync(0xffffffffu, sum_r, 2);
        sum_8 += __shfl_xor_sync(0xffffffffu, sum_8, 1);
        sum_8 += __shfl_xor_sync(0xffffffffu, sum_8, 2);
        l_r = l_r * alpha_r + sum_r;
        l_8 = l_8 * alpha_8 + sum_8;

        // ---- O += P @ V  (P packed from registers; V via ldmatrix.trans) ----
#pragma unroll
        for (int kk = 0; kk < 4; kk++) {
            uint32_t pa[4];
            pa[0] = packh2(s[2 * kk][0],     s[2 * kk][1]);
            pa[1] = packh2(s[2 * kk][2],     s[2 * kk][3]);
            pa[2] = packh2(s[2 * kk + 1][0], s[2 * kk + 1][1]);
            pa[3] = packh2(s[2 * kk + 1][2], s[2 * kk + 1][3]);
            uint32_t vf[8][2];
#pragma unroll
            for (int ng = 0; ng < 4; ng++) {
                int vrow = kk * 16 + (lane & 7) + ((lane & 8) ? 8 : 0);
                int vcol = ng * 16 + ((lane & 16) ? 8 : 0);
                uint32_t r0, r1, r2, r3;
                ldm4t(r0, r1, r2, r3, vbb + (vrow * FSTR + vcol) * 2);
                vf[2 * ng][0] = r0;     vf[2 * ng][1] = r1;
                vf[2 * ng + 1][0] = r2; vf[2 * ng + 1][1] = r3;
            }
#pragma unroll
            for (int nt = 0; nt < 8; nt++)
                mma_f16(o[nt], pa, vf[nt][0], vf[nt][1]);
        }
        __syncthreads();
        if (t + 2 < LKV_ / 64) load_kv(t & 1, (t + 2) * 64);
        cp_commit();
    }

    // ---- normalize, write AO half in concat layout ----
    float inv_r = 1.f / l_r, inv_8 = 1.f / l_8;
    int qg = q0 + w * 16 + g;
    __half* Obase = AO + ((size_t)(b * LQ_ + qg)) * DMODEL + h * DK_;
#pragma unroll
    for (int nt = 0; nt < 8; nt++) {
        int col = nt * 8 + 2 * c;
        *reinterpret_cast<__half2*>(Obase + col) =
            __floats2half2_rn(o[nt][0] * inv_r, o[nt][1] * inv_r);
        *reinterpret_cast<__half2*>(Obase + (size_t)8 * DMODEL + col) =
            __floats2half2_rn(o[nt][2] * inv_8, o[nt][3] * inv_8);
    }
}

// ---------------- launch ----------------
extern "C" void kernel_launch(void* const* d_in, const int* in_sizes, int n_in,
                              void* d_out, int out_size)
{
    (void)in_sizes; (void)n_in; (void)out_size;
    const float* q  = (const float*)d_in[0];
    const float* k  = (const float*)d_in[1];
    const float* v  = (const float*)d_in[2];
    const float* Wq = (const float*)d_in[3];
    const float* bq = (const float*)d_in[4];
    const float* Wk = (const float*)d_in[5];
    const float* bk = (const float*)d_in[6];
    const float* Wv = (const float*)d_in[7];
    const float* bv = (const float*)d_in[8];
    const float* Wo = (const float*)d_in[9];
    const float* bo = (const float*)d_in[10];
    float* out = (float*)d_out;

    __half *qr, *kr, *vr, *Wqt, *Wkt, *Wvt, *Wot, *Qp, *Kp, *Vp, *AO;
    cudaGetSymbolAddress((void**)&qr,  g_qr);
    cudaGetSymbolAddress((void**)&kr,  g_kr);
    cudaGetSymbolAddress((void**)&vr,  g_vr);
    cudaGetSymbolAddress((void**)&Wqt, g_Wqt);
    cudaGetSymbolAddress((void**)&Wkt, g_Wkt);
    cudaGetSymbolAddress((void**)&Wvt, g_Wvt);
    cudaGetSymbolAddress((void**)&Wot, g_Wot);
    cudaGetSymbolAddress((void**)&Qp,  g_Qp);
    cudaGetSymbolAddress((void**)&Kp,  g_Kp);
    cudaGetSymbolAddress((void**)&Vp,  g_Vp);
    cudaGetSymbolAddress((void**)&AO,  g_AO);

    cudaFuncSetAttribute(gemm_f16<true>,
                         cudaFuncAttributeMaxDynamicSharedMemorySize, GSMEM);
    cudaFuncSetAttribute(gemm_f16<false>,
                         cudaFuncAttributeMaxDynamicSharedMemorySize, GSMEM);
    cudaFuncSetAttribute(flash_f16,
                         cudaFuncAttributeMaxDynamicSharedMemorySize, FLASH_SMEM);

    // ---- round activations to half ----
    auto round_launch = [&](const float* src, __half* dst, size_t n) {
        int n4 = (int)(n / 4);
        round_half_kernel<<<(n4 + 255) / 256, 256>>>(src, dst, n4);
    };
    round_launch(q, qr, (size_t)B_SZ * LQ_  * DMODEL);
    round_launch(k, kr, (size_t)B_SZ * LKV_ * IMGM);
    round_launch(v, vr, (size_t)B_SZ * LKV_ * IMGM);

    // ---- weight transpose W[K,N] -> Wt[N,K] half ----
    transpose_half_kernel<<<dim3(DMODEL / 32, DMODEL / 32), dim3(32, 8)>>>(
        Wq, Wqt, DMODEL, DMODEL);
    transpose_half_kernel<<<dim3(DMODEL / 32, IMGM / 32), dim3(32, 8)>>>(
        Wk, Wkt, IMGM, DMODEL);
    transpose_half_kernel<<<dim3(DMODEL / 32, IMGM / 32), dim3(32, 8)>>>(
        Wv, Wvt, IMGM, DMODEL);
    transpose_half_kernel<<<dim3(DMODEL / 32, DMODEL / 32), dim3(32, 8)>>>(
        Wo, Wot, DMODEL, DMODEL);

    // ---- projections (half outputs) ----
    gemm_f16<true><<<dim3(DMODEL / GBN, (B_SZ * LQ_) / GBM), 256, GSMEM>>>(
        qr, Wqt, bq, Qp, B_SZ * LQ_, DMODEL, DMODEL);
    gemm_f16<true><<<dim3(DMODEL / GBN, (B_SZ * LKV_) / GBM), 256, GSMEM>>>(
        kr, Wkt, bk, Kp, B_SZ * LKV_, DMODEL, IMGM);
    gemm_f16<true><<<dim3(DMODEL / GBN, (B_SZ * LKV_) / GBM), 256, GSMEM>>>(
        vr, Wvt, bv, Vp, B_SZ * LKV_, DMODEL, IMGM);

    // ---- attention ----
    flash_f16<<<dim3(LQ_ / 128, HEADS_, B_SZ), 256, FLASH_SMEM>>>(
        Qp, Kp, Vp, AO);

    // ---- output projection (fp32 out) ----
    gemm_f16<false><<<dim3(DMODEL / GBN, (B_SZ * LQ_) / GBM), 256, GSMEM>>>(
        AO, Wot, bo, out, B_SZ * LQ_, DMODEL, DMODEL);
}

// round 5
// speedup vs baseline: 2.7454x; 1.0662x over previous
#include <cuda_runtime.h>
#include <cuda_fp16.h>
#include <cstdint>
#include <cstddef>

#define B_SZ   8
#define LQ_    2048
#define LKV_   1024
#define DMODEL 1024
#define IMGM   512
#define HEADS_ 16
#define DK_    64

// ---------------- scratch (no allocations allowed) ----------------
__device__ __half g_qr[(size_t)B_SZ * LQ_  * DMODEL];
__device__ __half g_kr[(size_t)B_SZ * LKV_ * IMGM];
__device__ __half g_vr[(size_t)B_SZ * LKV_ * IMGM];
__device__ __half g_Wqt[(size_t)DMODEL * DMODEL];   // W^T as half
__device__ __half g_Wkt[(size_t)DMODEL * IMGM];
__device__ __half g_Wvt[(size_t)DMODEL * IMGM];
__device__ __half g_Wot[(size_t)DMODEL * DMODEL];
__device__ __half g_Qp[(size_t)B_SZ * LQ_  * DMODEL];
__device__ __half g_Kp[(size_t)B_SZ * LKV_ * DMODEL];
__device__ __half g_Vp[(size_t)B_SZ * LKV_ * DMODEL];
__device__ __half g_AO[(size_t)B_SZ * LQ_  * DMODEL];

// ---------------- helpers ----------------
__device__ __forceinline__ void mma_f16(float d[4], const uint32_t a[4],
                                        uint32_t b0, uint32_t b1) {
    asm volatile(
        "mma.sync.aligned.m16n8k16.row.col.f32.f16.f16.f32 "
        "{%0,%1,%2,%3}, {%4,%5,%6,%7}, {%8,%9}, {%0,%1,%2,%3};"
        : "+f"(d[0]), "+f"(d[1]), "+f"(d[2]), "+f"(d[3])
        : "r"(a[0]), "r"(a[1]), "r"(a[2]), "r"(a[3]), "r"(b0), "r"(b1));
}

__device__ __forceinline__ void ldm4(uint32_t& r0, uint32_t& r1, uint32_t& r2,
                                     uint32_t& r3, uint32_t addr) {
    asm volatile("ldmatrix.sync.aligned.m8n8.x4.shared.b16 {%0,%1,%2,%3}, [%4];"
                 : "=r"(r0), "=r"(r1), "=r"(r2), "=r"(r3) : "r"(addr));
}
__device__ __forceinline__ void ldm4t(uint32_t& r0, uint32_t& r1, uint32_t& r2,
                                      uint32_t& r3, uint32_t addr) {
    asm volatile("ldmatrix.sync.aligned.m8n8.x4.trans.shared.b16 {%0,%1,%2,%3}, [%4];"
                 : "=r"(r0), "=r"(r1), "=r"(r2), "=r"(r3) : "r"(addr));
}

__device__ __forceinline__ void cp_async16(void* smem_dst, const void* gmem_src) {
    unsigned s = (unsigned)__cvta_generic_to_shared(smem_dst);
    asm volatile("cp.async.cg.shared.global [%0], [%1], 16;\n" :: "r"(s), "l"(gmem_src));
}
__device__ __forceinline__ void cp_commit() {
    asm volatile("cp.async.commit_group;\n");
}
template <int N> __device__ __forceinline__ void cp_wait() {
    asm volatile("cp.async.wait_group %0;\n" :: "n"(N));
}

__device__ __forceinline__ uint32_t packh2(float a, float b) {
    __half2 h = __floats2half2_rn(a, b);
    return *reinterpret_cast<uint32_t*>(&h);
}

// ---------------- elementwise round to half ----------------
__global__ __launch_bounds__(256) void round_half_kernel(
    const float* __restrict__ in, __half* __restrict__ out, int n4)
{
    int i = blockIdx.x * blockDim.x + threadIdx.x;
    if (i < n4) {
        float4 v = reinterpret_cast<const float4*>(in)[i];
        reinterpret_cast<__half2*>(out)[2 * i]     = __floats2half2_rn(v.x, v.y);
        reinterpret_cast<__half2*>(out)[2 * i + 1] = __floats2half2_rn(v.z, v.w);
    }
}

// ---------------- transpose + round: in[K][N] f32 -> out[N][K] half ----------------
__global__ __launch_bounds__(256) void transpose_half_kernel(
    const float* __restrict__ in, __half* __restrict__ out, int K, int N)
{
    __shared__ float tile[32][33];
    int k0 = blockIdx.y * 32, n0 = blockIdx.x * 32;
    int tx = threadIdx.x, ty = threadIdx.y;
#pragma unroll
    for (int i = ty; i < 32; i += 8)
        tile[i][tx] = in[(size_t)(k0 + i) * N + n0 + tx];
    __syncthreads();
#pragma unroll
    for (int i = ty; i < 32; i += 8)
        out[(size_t)(n0 + i) * K + k0 + tx] = __float2half_rn(tile[tx][i]);
}

// ---------------- fp16 GEMM: C[M,N] = (A[M,K] @ Bt[N,K]^T + bias) * oscale ----------------
// 128x128 tile, BK=32 halves, 4-stage cp.async, single barrier per k-iter.
#define GBM 128
#define GBN 128
#define GBK 32
#define GSTG 4
#define ASTR 40                       // halves per smem row (32 + 8 pad)
#define ATILE (GBM * ASTR)            // halves per stage (A or B)
#define GSMEM (2 * GSTG * ATILE * 2)  // bytes = 81920

template <bool HALF_OUT>
__global__ __launch_bounds__(256, 2) void gemm_f16(
    const __half* __restrict__ A, const __half* __restrict__ Bt,
    const float* __restrict__ bias, void* __restrict__ Cp,
    int M, int N, int K, float oscale)
{
    extern __shared__ __half smh[];
    __half* sA = smh;
    __half* sB = smh + GSTG * ATILE;
    const uint32_t sAb = (uint32_t)__cvta_generic_to_shared(sA);
    const uint32_t sBb = (uint32_t)__cvta_generic_to_shared(sB);

    const int tid = threadIdx.x;
    const int warp = tid >> 5, lane = tid & 31;
    const int wm = warp & 3, wn = warp >> 2;
    const int g = lane >> 2, c = lane & 3;
    const int m0 = blockIdx.y * GBM, n0 = blockIdx.x * GBN;

    auto load_stage = [&](int t, int s) {
#pragma unroll
        for (int p = 0; p < 2; p++) {
            int idx = tid + p * 256;
            int row = idx >> 2, ch = idx & 3;
            cp_async16(sA + s * ATILE + row * ASTR + ch * 8,
                       A + (size_t)(m0 + row) * K + t * GBK + ch * 8);
        }
#pragma unroll
        for (int p = 0; p < 2; p++) {
            int idx = tid + p * 256;
            int row = idx >> 2, ch = idx & 3;
            cp_async16(sB + s * ATILE + row * ASTR + ch * 8,
                       Bt + (size_t)(n0 + row) * K + t * GBK + ch * 8);
        }
    };

    float acc[2][8][4];
#pragma unroll
    for (int i = 0; i < 2; i++)
#pragma unroll
        for (int j = 0; j < 8; j++)
#pragma unroll
            for (int t = 0; t < 4; t++) acc[i][j][t] = 0.f;

    const int T = K / GBK;
    // prologue: tiles 0..2 into slots 0..2 (3 groups)
    load_stage(0, 0); cp_commit();
    load_stage(1, 1); cp_commit();
    load_stage(2, 2); cp_commit();

    int slot = 0;
    for (int t = 0; t < T; t++) {
        cp_wait<2>();          // tile t landed
        __syncthreads();       // all warps done with iter t-1 (frees slot (t+3)%4)
        const uint32_t ab = sAb + slot * ATILE * 2;
        const uint32_t bb = sBb + slot * ATILE * 2;

#pragma unroll
        for (int kk = 0; kk < 2; kk++) {
            uint32_t af[2][4];
#pragma unroll
            for (int mt = 0; mt < 2; mt++) {
                int lrow = wm * 32 + mt * 16 + (lane & 15);
                int lcol = kk * 16 + (lane >> 4) * 8;
                ldm4(af[mt][0], af[mt][1], af[mt][2], af[mt][3],
                     ab + (lrow * ASTR + lcol) * 2);
            }
            uint32_t bf[8][2];
#pragma unroll
            for (int ng = 0; ng < 4; ng++) {
                int nrow = wn * 64 + ng * 16 + (lane & 7) + ((lane & 16) ? 8 : 0);
                int ncol = kk * 16 + ((lane >> 3) & 1) * 8;
                uint32_t r0, r1, r2, r3;
                ldm4(r0, r1, r2, r3, bb + (nrow * ASTR + ncol) * 2);
                bf[2 * ng][0] = r0;     bf[2 * ng][1] = r1;
                bf[2 * ng + 1][0] = r2; bf[2 * ng + 1][1] = r3;
            }
#pragma unroll
            for (int mt = 0; mt < 2; mt++)
#pragma unroll
                for (int nt = 0; nt < 8; nt++)
                    mma_f16(acc[mt][nt], af[mt], bf[nt][0], bf[nt][1]);
        }
        // bottom: refill slot (t+3)%4 (read finished at iter t-1, covered by the sync above)
        if (t + 3 < T) load_stage(t + 3, (t + 3) & 3);
        cp_commit();
        slot = (slot + 1) & 3;
    }

    // epilogue
#pragma unroll
    for (int mt = 0; mt < 2; mt++) {
        int row = m0 + wm * 32 + mt * 16 + g;
#pragma unroll
        for (int nt = 0; nt < 8; nt++) {
            int col = n0 + wn * 64 + nt * 8 + 2 * c;
            float2 bv = *reinterpret_cast<const float2*>(bias + col);
            float v0 = (acc[mt][nt][0] + bv.x) * oscale;
            float v1 = (acc[mt][nt][1] + bv.y) * oscale;
            float v2 = (acc[mt][nt][2] + bv.x) * oscale;
            float v3 = (acc[mt][nt][3] + bv.y) * oscale;
            if (HALF_OUT) {
                __half* C = (__half*)Cp;
                *reinterpret_cast<__half2*>(C + (size_t)row * N + col) =
                    __floats2half2_rn(v0, v1);
                *reinterpret_cast<__half2*>(C + (size_t)(row + 8) * N + col) =
                    __floats2half2_rn(v2, v3);
            } else {
                float* C = (float*)Cp;
                *reinterpret_cast<float2*>(C + (size_t)row * N + col) =
                    make_float2(v0, v1);
                *reinterpret_cast<float2*>(C + (size_t)(row + 8) * N + col) =
                    make_float2(v2, v3);
            }
        }
    }
}

// ---------------- fp16 flash attention ----------------
// Block = (b, h, 128 Q rows). 256 threads = 8 warps. KV tiles of 64 rows in a
// 3-stage cp.async ring -> single barrier per iteration. Q is pre-scaled by
// 0.125*log2(e) in the Q-projection, so softmax uses bare exp2f.
#define FSTR 72                       // halves per smem row (64 + 8 pad)
#define KTILE (64 * FSTR)             // halves per K or V stage
#define FSTG 3
#define FLASH_SMEM ((2 * FSTG * KTILE + 128 * FSTR) * 2)  // 73728 B

__global__ __launch_bounds__(256, 2) void flash_f16(
    const __half* __restrict__ Qp, const __half* __restrict__ Kp,
    const __half* __restrict__ Vp, __half* __restrict__ AO)
{
    extern __shared__ __half smh[];
    __half* sK = smh;
    __half* sV = smh + FSTG * KTILE;
    __half* sQ = smh + 2 * FSTG * KTILE;
    const uint32_t sKb = (uint32_t)__cvta_generic_to_shared(sK);
    const uint32_t sVb = (uint32_t)__cvta_generic_to_shared(sV);
    const uint32_t sQb = (uint32_t)__cvta_generic_to_shared(sQ);

    const int tid = threadIdx.x;
    const int w = tid >> 5, lane = tid & 31;
    const int g = lane >> 2, c = lane & 3;
    const int q0 = blockIdx.x * 128, h = blockIdx.y, b = blockIdx.z;

    const __half* Qbase = Qp + ((size_t)(b * LQ_ + q0)) * DMODEL + h * DK_;
    const __half* Kbase = Kp + ((size_t)b * LKV_) * DMODEL + h * DK_;
    const __half* Vbase = Vp + ((size_t)b * LKV_) * DMODEL + h * DK_;

    auto load_kv = [&](int s, int kv0) {
#pragma unroll
        for (int p = 0; p < 2; p++) {
            int idx = tid + p * 256;
            int row = idx >> 3, ch = idx & 7;
            cp_async16(sK + s * KTILE + row * FSTR + ch * 8,
                       Kbase + (size_t)(kv0 + row) * DMODEL + ch * 8);
        }
#pragma unroll
        for (int p = 0; p < 2; p++) {
            int idx = tid + p * 256;
            int row = idx >> 3, ch = idx & 7;
            cp_async16(sV + s * KTILE + row * FSTR + ch * 8,
                       Vbase + (size_t)(kv0 + row) * DMODEL + ch * 8);
        }
    };

    // prologue: Q, kv0, kv1 (3 groups)
#pragma unroll
    for (int p = 0; p < 4; p++) {
        int idx = tid + p * 256;
        int row = idx >> 3, ch = idx & 7;
        cp_async16(sQ + row * FSTR + ch * 8,
                   Qbase + (size_t)row * DMODEL + ch * 8);
    }
    cp_commit();
    load_kv(0, 0);  cp_commit();
    load_kv(1, 64); cp_commit();

    cp_wait<2>();                 // Q ready
    __syncthreads();

    uint32_t qa[4][4];
#pragma unroll
    for (int kk = 0; kk < 4; kk++) {
        int lrow = w * 16 + (lane & 15);
        int lcol = kk * 16 + (lane >> 4) * 8;
        ldm4(qa[kk][0], qa[kk][1], qa[kk][2], qa[kk][3],
             sQb + (lrow * FSTR + lcol) * 2);
    }

    float o[8][4];
#pragma unroll
    for (int i = 0; i < 8; i++)
#pragma unroll
        for (int j = 0; j < 4; j++) o[i][j] = 0.f;

    float m_r = -1e30f, m_8 = -1e30f, l_r = 0.f, l_8 = 0.f;

    int slot = 0;
    for (int t = 0; t < LKV_ / 64; t++) {
        cp_wait<1>();             // KV tile t landed
        __syncthreads();          // all warps done with iter t-1
        const uint32_t kb  = sKb + slot * KTILE * 2;
        const uint32_t vbb = sVb + slot * KTILE * 2;

        // ---- S = Q @ K^T  (already in log2 domain: Q pre-scaled) ----
        float s[8][4];
#pragma unroll
        for (int i = 0; i < 8; i++)
#pragma unroll
            for (int j = 0; j < 4; j++) s[i][j] = 0.f;
#pragma unroll
        for (int kk = 0; kk < 4; kk++) {
            uint32_t bf[8][2];
#pragma unroll
            for (int ng = 0; ng < 4; ng++) {
                int nrow = ng * 16 + (lane & 7) + ((lane & 16) ? 8 : 0);
                int ncol = kk * 16 + ((lane >> 3) & 1) * 8;
                uint32_t r0, r1, r2, r3;
                ldm4(r0, r1, r2, r3, kb + (nrow * FSTR + ncol) * 2);
                bf[2 * ng][0] = r0;     bf[2 * ng][1] = r1;
                bf[2 * ng + 1][0] = r2; bf[2 * ng + 1][1] = r3;
            }
#pragma unroll
            for (int nt = 0; nt < 8; nt++)
                mma_f16(s[nt], qa[kk], bf[nt][0], bf[nt][1]);
        }

        // ---- online softmax (base-2) ----
        float cr = -1e30f, c8 = -1e30f;
#pragma unroll
        for (int nt = 0; nt < 8; nt++) {
            cr = fmaxf(cr, fmaxf(s[nt][0], s[nt][1]));
            c8 = fmaxf(c8, fmaxf(s[nt][2], s[nt][3]));
        }
        cr = fmaxf(cr, __shfl_xor_sync(0xffffffffu, cr, 1));
        cr = fmaxf(cr, __shfl_xor_sync(0xffffffffu, cr, 2));
        c8 = fmaxf(c8, __shfl_xor_sync(0xffffffffu, c8, 1));
        c8 = fmaxf(c8, __shfl_xor_sync(0xffffffffu, c8, 2));
        float mn_r = fmaxf(m_r, cr);
        float mn_8 = fmaxf(m_8, c8);
        float alpha_r = exp2f(m_r - mn_r);
        float alpha_8 = exp2f(m_8 - mn_8);
        m_r = mn_r; m_8 = mn_8;

        float sum_r = 0.f, sum_8 = 0.f;
#pragma unroll
        for (int nt = 0; nt < 8; nt++) {
            s[nt][0] = exp2f(s[nt][0] - m_r);
            s[nt][1] = exp2f(s[nt][1] - m_r);
            s[nt][2] = exp2f(s[nt][2] - m_8);
            s[nt][3] = exp2f(s[nt][3] - m_8);
            sum_r += s[nt][0] + s[nt][1];
            sum_8 += s[nt][2] + s[nt][3];
            o[nt][0] *= alpha_r; o[nt][1] *= alpha_r;
            o[nt][2] *= alpha_8; o[nt][3] *= alpha_8;
        }
        sum_r += __shfl_xor_sync(0xffffffffu, sum_r, 1);
        sum_r += __shfl_xor_sync(0xffffffffu, sum_r, 2);
        sum_8 += __shfl_xor_sync(0xffffffffu, sum_8, 1);
        sum_8 += __shfl_xor_sync(0xffffffffu, sum_8, 2);
        l_r = l_r * alpha_r + sum_r;
        l_8 = l_8 * alpha_8 + sum_8;

        // ---- O += P @ V  (P packed from registers; V via ldmatrix.trans) ----
#pragma unroll
        for (int kk = 0; kk < 4; kk++) {
            uint32_t pa[4];
            pa[0] = packh2(s[2 * kk][0],     s[2 * kk][1]);
            pa[1] = packh2(s[2 * kk][2],     s[2 * kk][3]);
            pa[2] = packh2(s[2 * kk + 1][0], s[2 * kk + 1][1]);
            pa[3] = packh2(s[2 * kk + 1][2], s[2 * kk + 1][3]);
            uint32_t vf[8][2];
#pragma unroll
            for (int ng = 0; ng < 4; ng++) {
                int vrow = kk * 16 + (lane & 7) + ((lane & 8) ? 8 : 0);
                int vcol = ng * 16 + ((lane & 16) ? 8 : 0);
                uint32_t r0, r1, r2, r3;
                ldm4t(r0, r1, r2, r3, vbb + (vrow * FSTR + vcol) * 2);
                vf[2 * ng][0] = r0;     vf[2 * ng][1] = r1;
                vf[2 * ng + 1][0] = r2; vf[2 * ng + 1][1] = r3;
            }
#pragma unroll
            for (int nt = 0; nt < 8; nt++)
                mma_f16(o[nt], pa, vf[nt][0], vf[nt][1]);
        }
        // bottom: refill slot (t+2)%3 (its readers finished at iter t-1, covered above)
        if (t + 2 < LKV_ / 64) load_kv((t + 2) % 3, (t + 2) * 64);
        cp_commit();
        slot = (slot + 1 == FSTG) ? 0 : slot + 1;
    }

    // ---- normalize, write AO half in concat layout ----
    float inv_r = 1.f / l_r, inv_8 = 1.f / l_8;
    int qg = q0 + w * 16 + g;
    __half* Obase = AO + ((size_t)(b * LQ_ + qg)) * DMODEL + h * DK_;
#pragma unroll
    for (int nt = 0; nt < 8; nt++) {
        int col = nt * 8 + 2 * c;
        *reinterpret_cast<__half2*>(Obase + col) =
            __floats2half2_rn(o[nt][0] * inv_r, o[nt][1] * inv_r);
        *reinterpret_cast<__half2*>(Obase + (size_t)8 * DMODEL + col) =
            __floats2half2_rn(o[nt][2] * inv_8, o[nt][3] * inv_8);
    }
}

// ---------------- launch ----------------
extern "C" void kernel_launch(void* const* d_in, const int* in_sizes, int n_in,
                              void* d_out, int out_size)
{
    (void)in_sizes; (void)n_in; (void)out_size;
    const float* q  = (const float*)d_in[0];
    const float* k  = (const float*)d_in[1];
    const float* v  = (const float*)d_in[2];
    const float* Wq = (const float*)d_in[3];
    const float* bq = (const float*)d_in[4];
    const float* Wk = (const float*)d_in[5];
    const float* bk = (const float*)d_in[6];
    const float* Wv = (const float*)d_in[7];
    const float* bv = (const float*)d_in[8];
    const float* Wo = (const float*)d_in[9];
    const float* bo = (const float*)d_in[10];
    float* out = (float*)d_out;

    __half *qr, *kr, *vr, *Wqt, *Wkt, *Wvt, *Wot, *Qp, *Kp, *Vp, *AO;
    cudaGetSymbolAddress((void**)&qr,  g_qr);
    cudaGetSymbolAddress((void**)&kr,  g_kr);
    cudaGetSymbolAddress((void**)&vr,  g_vr);
    cudaGetSymbolAddress((void**)&Wqt, g_Wqt);
    cudaGetSymbolAddress((void**)&Wkt, g_Wkt);
    cudaGetSymbolAddress((void**)&Wvt, g_Wvt);
    cudaGetSymbolAddress((void**)&Wot, g_Wot);
    cudaGetSymbolAddress((void**)&Qp,  g_Qp);
    cudaGetSymbolAddress((void**)&Kp,  g_Kp);
    cudaGetSymbolAddress((void**)&Vp,  g_Vp);
    cudaGetSymbolAddress((void**)&AO,  g_AO);

    cudaFuncSetAttribute(gemm_f16<true>,
                         cudaFuncAttributeMaxDynamicSharedMemorySize, GSMEM);
    cudaFuncSetAttribute(gemm_f16<false>,
                         cudaFuncAttributeMaxDynamicSharedMemorySize, GSMEM);
    cudaFuncSetAttribute(flash_f16,
                         cudaFuncAttributeMaxDynamicSharedMemorySize, FLASH_SMEM);

    // ---- round activations to half ----
    auto round_launch = [&](const float* src, __half* dst, size_t n) {
        int n4 = (int)(n / 4);
        round_half_kernel<<<(n4 + 255) / 256, 256>>>(src, dst, n4);
    };
    round_launch(q, qr, (size_t)B_SZ * LQ_  * DMODEL);
    round_launch(k, kr, (size_t)B_SZ * LKV_ * IMGM);
    round_launch(v, vr, (size_t)B_SZ * LKV_ * IMGM);

    // ---- weight transpose W[K,N] -> Wt[N,K] half ----
    transpose_half_kernel<<<dim3(DMODEL / 32, DMODEL / 32), dim3(32, 8)>>>(
        Wq, Wqt, DMODEL, DMODEL);
    transpose_half_kernel<<<dim3(DMODEL / 32, IMGM / 32), dim3(32, 8)>>>(
        Wk, Wkt, IMGM, DMODEL);
    transpose_half_kernel<<<dim3(DMODEL / 32, IMGM / 32), dim3(32, 8)>>>(
        Wv, Wvt, IMGM, DMODEL);
    transpose_half_kernel<<<dim3(DMODEL / 32, DMODEL / 32), dim3(32, 8)>>>(
        Wo, Wot, DMODEL, DMODEL);

    const float QSCALE = 0.125f * 1.4426950408889634f;  // (1/sqrt(64)) * log2(e)

    // ---- projections (half outputs; Q pre-scaled for base-2 softmax) ----
    gemm_f16<true><<<dim3(DMODEL / GBN, (B_SZ * LQ_) / GBM), 256, GSMEM>>>(
        qr, Wqt, bq, Qp, B_SZ * LQ_, DMODEL, DMODEL, QSCALE);
    gemm_f16<true><<<dim3(DMODEL / GBN, (B_SZ * LKV_) / GBM), 256, GSMEM>>>(
        kr, Wkt, bk, Kp, B_SZ * LKV_, DMODEL, IMGM, 1.0f);
    gemm_f16<true><<<dim3(DMODEL / GBN, (B_SZ * LKV_) / GBM), 256, GSMEM>>>(
        vr, Wvt, bv, Vp, B_SZ * LKV_, DMODEL, IMGM, 1.0f);

    // ---- attention ----
    flash_f16<<<dim3(LQ_ / 128, HEADS_, B_SZ), 256, FLASH_SMEM>>>(
        Qp, Kp, Vp, AO);

    // ---- output projection (fp32 out) ----
    gemm_f16<false><<<dim3(DMODEL / GBN, (B_SZ * LQ_) / GBM), 256, GSMEM>>>(
        AO, Wot, bo, out, B_SZ * LQ_, DMODEL, DMODEL, 1.0f);
}

// round 6
// speedup vs baseline: 2.8341x; 1.0323x over previous
#include <cuda_runtime.h>
#include <cuda_fp16.h>
#include <cstdint>
#include <cstddef>

#define B_SZ   8
#define LQ_    2048
#define LKV_   1024
#define DMODEL 1024
#define IMGM   512
#define HEADS_ 16
#define DK_    64

// ---------------- scratch (no allocations allowed) ----------------
__device__ __half g_qr[(size_t)B_SZ * LQ_  * DMODEL];
__device__ __half g_kr[(size_t)B_SZ * LKV_ * IMGM];
__device__ __half g_vr[(size_t)B_SZ * LKV_ * IMGM];
__device__ __half g_Wqt[(size_t)DMODEL * DMODEL];   // W^T as half
__device__ __half g_Wkt[(size_t)DMODEL * IMGM];
__device__ __half g_Wvt[(size_t)DMODEL * IMGM];
__device__ __half g_Wot[(size_t)DMODEL * DMODEL];
__device__ __half g_Qp[(size_t)B_SZ * LQ_  * DMODEL];
__device__ __half g_Kp[(size_t)B_SZ * LKV_ * DMODEL];
__device__ __half g_Vp[(size_t)B_SZ * LKV_ * DMODEL];
__device__ __half g_AO[(size_t)B_SZ * LQ_  * DMODEL];

// ---------------- helpers ----------------
__device__ __forceinline__ void mma_f16(float d[4], const uint32_t a[4],
                                        uint32_t b0, uint32_t b1) {
    asm volatile(
        "mma.sync.aligned.m16n8k16.row.col.f32.f16.f16.f32 "
        "{%0,%1,%2,%3}, {%4,%5,%6,%7}, {%8,%9}, {%0,%1,%2,%3};"
        : "+f"(d[0]), "+f"(d[1]), "+f"(d[2]), "+f"(d[3])
        : "r"(a[0]), "r"(a[1]), "r"(a[2]), "r"(a[3]), "r"(b0), "r"(b1));
}

__device__ __forceinline__ void ldm4(uint32_t& r0, uint32_t& r1, uint32_t& r2,
                                     uint32_t& r3, uint32_t addr) {
    asm volatile("ldmatrix.sync.aligned.m8n8.x4.shared.b16 {%0,%1,%2,%3}, [%4];"
                 : "=r"(r0), "=r"(r1), "=r"(r2), "=r"(r3) : "r"(addr));
}
__device__ __forceinline__ void ldm4t(uint32_t& r0, uint32_t& r1, uint32_t& r2,
                                      uint32_t& r3, uint32_t addr) {
    asm volatile("ldmatrix.sync.aligned.m8n8.x4.trans.shared.b16 {%0,%1,%2,%3}, [%4];"
                 : "=r"(r0), "=r"(r1), "=r"(r2), "=r"(r3) : "r"(addr));
}

__device__ __forceinline__ void cp_async16(void* smem_dst, const void* gmem_src) {
    unsigned s = (unsigned)__cvta_generic_to_shared(smem_dst);
    asm volatile("cp.async.cg.shared.global [%0], [%1], 16;\n" :: "r"(s), "l"(gmem_src));
}
__device__ __forceinline__ void cp_commit() {
    asm volatile("cp.async.commit_group;\n");
}
template <int N> __device__ __forceinline__ void cp_wait() {
    asm volatile("cp.async.wait_group %0;\n" :: "n"(N));
}

__device__ __forceinline__ uint32_t packh2(float a, float b) {
    __half2 h = __floats2half2_rn(a, b);
    return *reinterpret_cast<uint32_t*>(&h);
}

// ---------------- elementwise round to half ----------------
__global__ __launch_bounds__(256) void round_half_kernel(
    const float* __restrict__ in, __half* __restrict__ out, int n4)
{
    int i = blockIdx.x * blockDim.x + threadIdx.x;
    if (i < n4) {
        float4 v = reinterpret_cast<const float4*>(in)[i];
        reinterpret_cast<__half2*>(out)[2 * i]     = __floats2half2_rn(v.x, v.y);
        reinterpret_cast<__half2*>(out)[2 * i + 1] = __floats2half2_rn(v.z, v.w);
    }
}

// round k and v in one launch (z picks tensor)
__global__ __launch_bounds__(256) void round_kv_kernel(
    const float* __restrict__ k, const float* __restrict__ v,
    __half* __restrict__ kr, __half* __restrict__ vr, int n4)
{
    const float* in  = blockIdx.z ? v : k;
    __half*      out = blockIdx.z ? vr : kr;
    int i = blockIdx.x * blockDim.x + threadIdx.x;
    if (i < n4) {
        float4 t = reinterpret_cast<const float4*>(in)[i];
        reinterpret_cast<__half2*>(out)[2 * i]     = __floats2half2_rn(t.x, t.y);
        reinterpret_cast<__half2*>(out)[2 * i + 1] = __floats2half2_rn(t.z, t.w);
    }
}

// ---------------- all-weights transpose + round: W[K][1024] -> Wt[1024][K] ----------------
// z: 0=Wq(K=1024), 1=Wo(K=1024), 2=Wk(K=512), 3=Wv(K=512)
__global__ __launch_bounds__(256) void transpose_all_kernel(
    const float* __restrict__ Wq, const float* __restrict__ Wo,
    const float* __restrict__ Wk, const float* __restrict__ Wv,
    __half* __restrict__ Wqt, __half* __restrict__ Wot,
    __half* __restrict__ Wkt, __half* __restrict__ Wvt)
{
    const int z = blockIdx.z;
    const int K = (z < 2) ? DMODEL : IMGM;
    if (blockIdx.y * 32 >= K) return;
    const float* in  = (z == 0) ? Wq : (z == 1) ? Wo : (z == 2) ? Wk : Wv;
    __half*      out = (z == 0) ? Wqt : (z == 1) ? Wot : (z == 2) ? Wkt : Wvt;

    __shared__ float tile[32][33];
    int k0 = blockIdx.y * 32, n0 = blockIdx.x * 32;
    int tx = threadIdx.x, ty = threadIdx.y;
#pragma unroll
    for (int i = ty; i < 32; i += 8)
        tile[i][tx] = in[(size_t)(k0 + i) * DMODEL + n0 + tx];
    __syncthreads();
#pragma unroll
    for (int i = ty; i < 32; i += 8)
        out[(size_t)(n0 + i) * K + k0 + tx] = __float2half_rn(tile[tx][i]);
}

// ---------------- fp16 GEMM: C[M,N] = (A[M,K] @ Bt[N,K]^T + bias) * oscale ----------------
// 128x128 tile, BK=32 halves, 4-stage cp.async, single barrier per k-iter.
#define GBM 128
#define GBN 128
#define GBK 32
#define GSTG 4
#define ASTR 40                       // halves per smem row (32 + 8 pad)
#define ATILE (GBM * ASTR)            // halves per stage (A or B)
#define GSMEM (2 * GSTG * ATILE * 2)  // bytes = 81920

template <bool HALF_OUT, bool DUAL>
__global__ __launch_bounds__(256, 2) void gemm_f16(
    const __half* __restrict__ A0, const __half* __restrict__ Bt0,
    const float* __restrict__ bias0, void* __restrict__ Cp0,
    const __half* __restrict__ A1, const __half* __restrict__ Bt1,
    const float* __restrict__ bias1, void* __restrict__ Cp1,
    int M, int N, int K, float oscale)
{
    const __half* A    = (DUAL && blockIdx.z) ? A1 : A0;
    const __half* Bt   = (DUAL && blockIdx.z) ? Bt1 : Bt0;
    const float*  bias = (DUAL && blockIdx.z) ? bias1 : bias0;
    void*         Cp   = (DUAL && blockIdx.z) ? Cp1 : Cp0;

    extern __shared__ __half smh[];
    __half* sA = smh;
    __half* sB = smh + GSTG * ATILE;
    const uint32_t sAb = (uint32_t)__cvta_generic_to_shared(sA);
    const uint32_t sBb = (uint32_t)__cvta_generic_to_shared(sB);

    const int tid = threadIdx.x;
    const int warp = tid >> 5, lane = tid & 31;
    const int wm = warp & 3, wn = warp >> 2;
    const int g = lane >> 2, c = lane & 3;
    const int m0 = blockIdx.y * GBM, n0 = blockIdx.x * GBN;

    auto load_stage = [&](int t, int s) {
#pragma unroll
        for (int p = 0; p < 2; p++) {
            int idx = tid + p * 256;
            int row = idx >> 2, ch = idx & 3;
            cp_async16(sA + s * ATILE + row * ASTR + ch * 8,
                       A + (size_t)(m0 + row) * K + t * GBK + ch * 8);
        }
#pragma unroll
        for (int p = 0; p < 2; p++) {
            int idx = tid + p * 256;
            int row = idx >> 2, ch = idx & 3;
            cp_async16(sB + s * ATILE + row * ASTR + ch * 8,
                       Bt + (size_t)(n0 + row) * K + t * GBK + ch * 8);
        }
    };

    float acc[2][8][4];
#pragma unroll
    for (int i = 0; i < 2; i++)
#pragma unroll
        for (int j = 0; j < 8; j++)
#pragma unroll
            for (int t = 0; t < 4; t++) acc[i][j][t] = 0.f;

    const int T = K / GBK;
    load_stage(0, 0); cp_commit();
    load_stage(1, 1); cp_commit();
    load_stage(2, 2); cp_commit();

    int slot = 0;
    for (int t = 0; t < T; t++) {
        cp_wait<2>();          // tile t landed
        __syncthreads();       // all warps done with iter t-1 (frees slot (t+3)%4)
        const uint32_t ab = sAb + slot * ATILE * 2;
        const uint32_t bb = sBb + slot * ATILE * 2;

#pragma unroll
        for (int kk = 0; kk < 2; kk++) {
            uint32_t af[2][4];
#pragma unroll
            for (int mt = 0; mt < 2; mt++) {
                int lrow = wm * 32 + mt * 16 + (lane & 15);
                int lcol = kk * 16 + (lane >> 4) * 8;
                ldm4(af[mt][0], af[mt][1], af[mt][2], af[mt][3],
                     ab + (lrow * ASTR + lcol) * 2);
            }
            uint32_t bf[8][2];
#pragma unroll
            for (int ng = 0; ng < 4; ng++) {
                int nrow = wn * 64 + ng * 16 + (lane & 7) + ((lane & 16) ? 8 : 0);
                int ncol = kk * 16 + ((lane >> 3) & 1) * 8;
                uint32_t r0, r1, r2, r3;
                ldm4(r0, r1, r2, r3, bb + (nrow * ASTR + ncol) * 2);
                bf[2 * ng][0] = r0;     bf[2 * ng][1] = r1;
                bf[2 * ng + 1][0] = r2; bf[2 * ng + 1][1] = r3;
            }
#pragma unroll
            for (int mt = 0; mt < 2; mt++)
#pragma unroll
                for (int nt = 0; nt < 8; nt++)
                    mma_f16(acc[mt][nt], af[mt], bf[nt][0], bf[nt][1]);
        }
        if (t + 3 < T) load_stage(t + 3, (t + 3) & 3);
        cp_commit();
        slot = (slot + 1) & 3;
    }

    // epilogue
#pragma unroll
    for (int mt = 0; mt < 2; mt++) {
        int row = m0 + wm * 32 + mt * 16 + g;
#pragma unroll
        for (int nt = 0; nt < 8; nt++) {
            int col = n0 + wn * 64 + nt * 8 + 2 * c;
            float2 bv = *reinterpret_cast<const float2*>(bias + col);
            float v0 = (acc[mt][nt][0] + bv.x) * oscale;
            float v1 = (acc[mt][nt][1] + bv.y) * oscale;
            float v2 = (acc[mt][nt][2] + bv.x) * oscale;
            float v3 = (acc[mt][nt][3] + bv.y) * oscale;
            if (HALF_OUT) {
                __half* C = (__half*)Cp;
                *reinterpret_cast<__half2*>(C + (size_t)row * N + col) =
                    __floats2half2_rn(v0, v1);
                *reinterpret_cast<__half2*>(C + (size_t)(row + 8) * N + col) =
                    __floats2half2_rn(v2, v3);
            } else {
                float* C = (float*)Cp;
                *reinterpret_cast<float2*>(C + (size_t)row * N + col) =
                    make_float2(v0, v1);
                *reinterpret_cast<float2*>(C + (size_t)(row + 8) * N + col) =
                    make_float2(v2, v3);
            }
        }
    }
}

// ---------------- fp16 flash attention ----------------
// Block = (b, h, 128 Q rows). 256 threads = 8 warps. KV tiles of 64 rows in a
// 3-stage cp.async ring -> single barrier per iteration. Q is pre-scaled by
// 0.125*log2(e) in the Q-projection, so softmax uses bare exp2f.
#define FSTR 72                       // halves per smem row (64 + 8 pad)
#define KTILE (64 * FSTR)             // halves per K or V stage
#define FSTG 3
#define FLASH_SMEM ((2 * FSTG * KTILE + 128 * FSTR) * 2)  // 73728 B

__global__ __launch_bounds__(256, 2) void flash_f16(
    const __half* __restrict__ Qp, const __half* __restrict__ Kp,
    const __half* __restrict__ Vp, __half* __restrict__ AO)
{
    extern __shared__ __half smh[];
    __half* sK = smh;
    __half* sV = smh + FSTG * KTILE;
    __half* sQ = smh + 2 * FSTG * KTILE;
    const uint32_t sKb = (uint32_t)__cvta_generic_to_shared(sK);
    const uint32_t sVb = (uint32_t)__cvta_generic_to_shared(sV);
    const uint32_t sQb = (uint32_t)__cvta_generic_to_shared(sQ);

    const int tid = threadIdx.x;
    const int w = tid >> 5, lane = tid & 31;
    const int g = lane >> 2, c = lane & 3;
    const int q0 = blockIdx.x * 128, h = blockIdx.y, b = blockIdx.z;

    const __half* Qbase = Qp + ((size_t)(b * LQ_ + q0)) * DMODEL + h * DK_;
    const __half* Kbase = Kp + ((size_t)b * LKV_) * DMODEL + h * DK_;
    const __half* Vbase = Vp + ((size_t)b * LKV_) * DMODEL + h * DK_;

    auto load_kv = [&](int s, int kv0) {
#pragma unroll
        for (int p = 0; p < 2; p++) {
            int idx = tid + p * 256;
            int row = idx >> 3, ch = idx & 7;
            cp_async16(sK + s * KTILE + row * FSTR + ch * 8,
                       Kbase + (size_t)(kv0 + row) * DMODEL + ch * 8);
        }
#pragma unroll
        for (int p = 0; p < 2; p++) {
            int idx = tid + p * 256;
            int row = idx >> 3, ch = idx & 7;
            cp_async16(sV + s * KTILE + row * FSTR + ch * 8,
                       Vbase + (size_t)(kv0 + row) * DMODEL + ch * 8);
        }
    };

    // prologue: Q, kv0, kv1 (3 groups)
#pragma unroll
    for (int p = 0; p < 4; p++) {
        int idx = tid + p * 256;
        int row = idx >> 3, ch = idx & 7;
        cp_async16(sQ + row * FSTR + ch * 8,
                   Qbase + (size_t)row * DMODEL + ch * 8);
    }
    cp_commit();
    load_kv(0, 0);  cp_commit();
    load_kv(1, 64); cp_commit();

    cp_wait<2>();                 // Q ready
    __syncthreads();

    uint32_t qa[4][4];
#pragma unroll
    for (int kk = 0; kk < 4; kk++) {
        int lrow = w * 16 + (lane & 15);
        int lcol = kk * 16 + (lane >> 4) * 8;
        ldm4(qa[kk][0], qa[kk][1], qa[kk][2], qa[kk][3],
             sQb + (lrow * FSTR + lcol) * 2);
    }

    float o[8][4];
#pragma unroll
    for (int i = 0; i < 8; i++)
#pragma unroll
        for (int j = 0; j < 4; j++) o[i][j] = 0.f;

    float m_r = -1e30f, m_8 = -1e30f, l_r = 0.f, l_8 = 0.f;

    int slot = 0;
    for (int t = 0; t < LKV_ / 64; t++) {
        cp_wait<1>();             // KV tile t landed
        __syncthreads();          // all warps done with iter t-1
        const uint32_t kb  = sKb + slot * KTILE * 2;
        const uint32_t vbb = sVb + slot * KTILE * 2;

        // ---- S = Q @ K^T  (already in log2 domain: Q pre-scaled) ----
        float s[8][4];
#pragma unroll
        for (int i = 0; i < 8; i++)
#pragma unroll
            for (int j = 0; j < 4; j++) s[i][j] = 0.f;
#pragma unroll
        for (int kk = 0; kk < 4; kk++) {
            uint32_t bf[8][2];
#pragma unroll
            for (int ng = 0; ng < 4; ng++) {
                int nrow = ng * 16 + (lane & 7) + ((lane & 16) ? 8 : 0);
                int ncol = kk * 16 + ((lane >> 3) & 1) * 8;
                uint32_t r0, r1, r2, r3;
                ldm4(r0, r1, r2, r3, kb + (nrow * FSTR + ncol) * 2);
                bf[2 * ng][0] = r0;     bf[2 * ng][1] = r1;
                bf[2 * ng + 1][0] = r2; bf[2 * ng + 1][1] = r3;
            }
#pragma unroll
            for (int nt = 0; nt < 8; nt++)
                mma_f16(s[nt], qa[kk], bf[nt][0], bf[nt][1]);
        }

        // ---- online softmax (base-2) ----
        float cr = -1e30f, c8 = -1e30f;
#pragma unroll
        for (int nt = 0; nt < 8; nt++) {
            cr = fmaxf(cr, fmaxf(s[nt][0], s[nt][1]));
            c8 = fmaxf(c8, fmaxf(s[nt][2], s[nt][3]));
        }
        cr = fmaxf(cr, __shfl_xor_sync(0xffffffffu, cr, 1));
        cr = fmaxf(cr, __shfl_xor_sync(0xffffffffu, cr, 2));
        c8 = fmaxf(c8, __shfl_xor_sync(0xffffffffu, c8, 1));
        c8 = fmaxf(c8, __shfl_xor_sync(0xffffffffu, c8, 2));
        float mn_r = fmaxf(m_r, cr);
        float mn_8 = fmaxf(m_8, c8);
        float alpha_r = exp2f(m_r - mn_r);
        float alpha_8 = exp2f(m_8 - mn_8);
        m_r = mn_r; m_8 = mn_8;

        float sum_r = 0.f, sum_8 = 0.f;
#pragma unroll
        for (int nt = 0; nt < 8; nt++) {
            s[nt][0] = exp2f(s[nt][0] - m_r);
            s[nt][1] = exp2f(s[nt][1] - m_r);
            s[nt][2] = exp2f(s[nt][2] - m_8);
            s[nt][3] = exp2f(s[nt][3] - m_8);
            sum_r += s[nt][0] + s[nt][1];
            sum_8 += s[nt][2] + s[nt][3];
            o[nt][0] *= alpha_r; o[nt][1] *= alpha_r;
            o[nt][2] *= alpha_8; o[nt][3] *= alpha_8;
        }
        sum_r += __shfl_xor_sync(0xffffffffu, sum_r, 1);
        sum_r += __shfl_xor_sync(0xffffffffu, sum_r, 2);
        sum_8 += __shfl_xor_sync(0xffffffffu, sum_8, 1);
        sum_8 += __shfl_xor_sync(0xffffffffu, sum_8, 2);
        l_r = l_r * alpha_r + sum_r;
        l_8 = l_8 * alpha_8 + sum_8;

        // ---- O += P @ V  (P packed from registers; V via ldmatrix.trans) ----
#pragma unroll
        for (int kk = 0; kk < 4; kk++) {
            uint32_t pa[4];
            pa[0] = packh2(s[2 * kk][0],     s[2 * kk][1]);
            pa[1] = packh2(s[2 * kk][2],     s[2 * kk][3]);
            pa[2] = packh2(s[2 * kk + 1][0], s[2 * kk + 1][1]);
            pa[3] = packh2(s[2 * kk + 1][2], s[2 * kk + 1][3]);
            uint32_t vf[8][2];
#pragma unroll
            for (int ng = 0; ng < 4; ng++) {
                int vrow = kk * 16 + (lane & 7) + ((lane & 8) ? 8 : 0);
                int vcol = ng * 16 + ((lane & 16) ? 8 : 0);
                uint32_t r0, r1, r2, r3;
                ldm4t(r0, r1, r2, r3, vbb + (vrow * FSTR + vcol) * 2);
                vf[2 * ng][0] = r0;     vf[2 * ng][1] = r1;
                vf[2 * ng + 1][0] = r2; vf[2 * ng + 1][1] = r3;
            }
#pragma unroll
            for (int nt = 0; nt < 8; nt++)
                mma_f16(o[nt], pa, vf[nt][0], vf[nt][1]);
        }
        if (t + 2 < LKV_ / 64) load_kv((t + 2) % 3, (t + 2) * 64);
        cp_commit();
        slot = (slot + 1 == FSTG) ? 0 : slot + 1;
    }

    // ---- normalize, write AO half in concat layout ----
    float inv_r = 1.f / l_r, inv_8 = 1.f / l_8;
    int qg = q0 + w * 16 + g;
    __half* Obase = AO + ((size_t)(b * LQ_ + qg)) * DMODEL + h * DK_;
#pragma unroll
    for (int nt = 0; nt < 8; nt++) {
        int col = nt * 8 + 2 * c;
        *reinterpret_cast<__half2*>(Obase + col) =
            __floats2half2_rn(o[nt][0] * inv_r, o[nt][1] * inv_r);
        *reinterpret_cast<__half2*>(Obase + (size_t)8 * DMODEL + col) =
            __floats2half2_rn(o[nt][2] * inv_8, o[nt][3] * inv_8);
    }
}

// ---------------- launch ----------------
extern "C" void kernel_launch(void* const* d_in, const int* in_sizes, int n_in,
                              void* d_out, int out_size)
{
    (void)in_sizes; (void)n_in; (void)out_size;
    const float* q  = (const float*)d_in[0];
    const float* k  = (const float*)d_in[1];
    const float* v  = (const float*)d_in[2];
    const float* Wq = (const float*)d_in[3];
    const float* bq = (const float*)d_in[4];
    const float* Wk = (const float*)d_in[5];
    const float* bk = (const float*)d_in[6];
    const float* Wv = (const float*)d_in[7];
    const float* bv = (const float*)d_in[8];
    const float* Wo = (const float*)d_in[9];
    const float* bo = (const float*)d_in[10];
    float* out = (float*)d_out;

    __half *qr, *kr, *vr, *Wqt, *Wkt, *Wvt, *Wot, *Qp, *Kp, *Vp, *AO;
    cudaGetSymbolAddress((void**)&qr,  g_qr);
    cudaGetSymbolAddress((void**)&kr,  g_kr);
    cudaGetSymbolAddress((void**)&vr,  g_vr);
    cudaGetSymbolAddress((void**)&Wqt, g_Wqt);
    cudaGetSymbolAddress((void**)&Wkt, g_Wkt);
    cudaGetSymbolAddress((void**)&Wvt, g_Wvt);
    cudaGetSymbolAddress((void**)&Wot, g_Wot);
    cudaGetSymbolAddress((void**)&Qp,  g_Qp);
    cudaGetSymbolAddress((void**)&Kp,  g_Kp);
    cudaGetSymbolAddress((void**)&Vp,  g_Vp);
    cudaGetSymbolAddress((void**)&AO,  g_AO);

    cudaFuncSetAttribute((const void*)gemm_f16<true, false>,
                         cudaFuncAttributeMaxDynamicSharedMemorySize, GSMEM);
    cudaFuncSetAttribute((const void*)gemm_f16<true, true>,
                         cudaFuncAttributeMaxDynamicSharedMemorySize, GSMEM);
    cudaFuncSetAttribute((const void*)gemm_f16<false, false>,
                         cudaFuncAttributeMaxDynamicSharedMemorySize, GSMEM);
    cudaFuncSetAttribute((const void*)flash_f16,
                         cudaFuncAttributeMaxDynamicSharedMemorySize, FLASH_SMEM);

    // launch 1: round q
    {
        int n4 = (int)((size_t)B_SZ * LQ_ * DMODEL / 4);
        round_half_kernel<<<(n4 + 255) / 256, 256>>>(q, qr, n4);
    }
    // launch 2: round k and v together
    {
        int n4 = (int)((size_t)B_SZ * LKV_ * IMGM / 4);
        round_kv_kernel<<<dim3((n4 + 255) / 256, 1, 2), 256>>>(k, v, kr, vr, n4);
    }
    // launch 3: all weight transposes
    transpose_all_kernel<<<dim3(DMODEL / 32, DMODEL / 32, 4), dim3(32, 8)>>>(
        Wq, Wo, Wk, Wv, Wqt, Wot, Wkt, Wvt);

    const float QSCALE = 0.125f * 1.4426950408889634f;  // (1/sqrt(64)) * log2(e)

    // launch 4: Q projection (pre-scaled for base-2 softmax)
    gemm_f16<true, false><<<dim3(DMODEL / GBN, (B_SZ * LQ_) / GBM), 256, GSMEM>>>(
        qr, Wqt, bq, Qp, nullptr, nullptr, nullptr, nullptr,
        B_SZ * LQ_, DMODEL, DMODEL, QSCALE);

    // launch 5: K and V projections fused (z selects operand set)
    gemm_f16<true, true><<<dim3(DMODEL / GBN, (B_SZ * LKV_) / GBM, 2), 256, GSMEM>>>(
        kr, Wkt, bk, Kp, vr, Wvt, bv, Vp,
        B_SZ * LKV_, DMODEL, IMGM, 1.0f);

    // launch 6: attention (this is the ncu -s 5 capture slot)
    flash_f16<<<dim3(LQ_ / 128, HEADS_, B_SZ), 256, FLASH_SMEM>>>(
        Qp, Kp, Vp, AO);

    // launch 7: output projection (fp32 out)
    gemm_f16<false, false><<<dim3(DMODEL / GBN, (B_SZ * LQ_) / GBM), 256, GSMEM>>>(
        AO, Wot, bo, out, nullptr, nullptr, nullptr, nullptr,
        B_SZ * LQ_, DMODEL, DMODEL, 1.0f);
}

// round 7
// speedup vs baseline: 3.0997x; 1.0937x over previous
#include <cuda_runtime.h>
#include <cuda_fp16.h>
#include <cstdint>
#include <cstddef>

#define B_SZ   8
#define LQ_    2048
#define LKV_   1024
#define DMODEL 1024
#define IMGM   512
#define HEADS_ 16
#define DK_    64

// ---------------- scratch (no allocations allowed) ----------------
__device__ __half g_qr[(size_t)B_SZ * LQ_  * DMODEL];
__device__ __half g_kr[(size_t)B_SZ * LKV_ * IMGM];
__device__ __half g_vr[(size_t)B_SZ * LKV_ * IMGM];
__device__ __half g_Wqt[(size_t)DMODEL * DMODEL];   // W^T as half
__device__ __half g_Wkt[(size_t)DMODEL * IMGM];
__device__ __half g_Wvt[(size_t)DMODEL * IMGM];
__device__ __half g_Wot[(size_t)DMODEL * DMODEL];
__device__ __half g_Qp[(size_t)B_SZ * LQ_  * DMODEL];
__device__ __half g_Kp[(size_t)B_SZ * LKV_ * DMODEL];
__device__ __half g_Vp[(size_t)B_SZ * LKV_ * DMODEL];
__device__ __half g_AO[(size_t)B_SZ * LQ_  * DMODEL];

// ---------------- helpers ----------------
__device__ __forceinline__ void mma_f16(float d[4], const uint32_t a[4],
                                        uint32_t b0, uint32_t b1) {
    asm volatile(
        "mma.sync.aligned.m16n8k16.row.col.f32.f16.f16.f32 "
        "{%0,%1,%2,%3}, {%4,%5,%6,%7}, {%8,%9}, {%0,%1,%2,%3};"
        : "+f"(d[0]), "+f"(d[1]), "+f"(d[2]), "+f"(d[3])
        : "r"(a[0]), "r"(a[1]), "r"(a[2]), "r"(a[3]), "r"(b0), "r"(b1));
}

__device__ __forceinline__ void ldm4(uint32_t& r0, uint32_t& r1, uint32_t& r2,
                                     uint32_t& r3, uint32_t addr) {
    asm volatile("ldmatrix.sync.aligned.m8n8.x4.shared.b16 {%0,%1,%2,%3}, [%4];"
                 : "=r"(r0), "=r"(r1), "=r"(r2), "=r"(r3) : "r"(addr));
}
__device__ __forceinline__ void ldm4t(uint32_t& r0, uint32_t& r1, uint32_t& r2,
                                      uint32_t& r3, uint32_t addr) {
    asm volatile("ldmatrix.sync.aligned.m8n8.x4.trans.shared.b16 {%0,%1,%2,%3}, [%4];"
                 : "=r"(r0), "=r"(r1), "=r"(r2), "=r"(r3) : "r"(addr));
}

__device__ __forceinline__ void cp_async16(void* smem_dst, const void* gmem_src) {
    unsigned s = (unsigned)__cvta_generic_to_shared(smem_dst);
    asm volatile("cp.async.cg.shared.global [%0], [%1], 16;\n" :: "r"(s), "l"(gmem_src));
}
__device__ __forceinline__ void cp_commit() {
    asm volatile("cp.async.commit_group;\n");
}
template <int N> __device__ __forceinline__ void cp_wait() {
    asm volatile("cp.async.wait_group %0;\n" :: "n"(N));
}

__device__ __forceinline__ uint32_t packh2(float a, float b) {
    __half2 h = __floats2half2_rn(a, b);
    return *reinterpret_cast<uint32_t*>(&h);
}
__device__ __forceinline__ uint32_t h2exp2(uint32_t x) {
    uint32_t r;
    asm volatile("ex2.approx.f16x2 %0, %1;" : "=r"(r) : "r"(x));
    return r;
}

// ---------------- elementwise round to half ----------------
__global__ __launch_bounds__(256) void round_half_kernel(
    const float* __restrict__ in, __half* __restrict__ out, int n4)
{
    int i = blockIdx.x * blockDim.x + threadIdx.x;
    if (i < n4) {
        float4 v = reinterpret_cast<const float4*>(in)[i];
        reinterpret_cast<__half2*>(out)[2 * i]     = __floats2half2_rn(v.x, v.y);
        reinterpret_cast<__half2*>(out)[2 * i + 1] = __floats2half2_rn(v.z, v.w);
    }
}

// round k and v in one launch (z picks tensor)
__global__ __launch_bounds__(256) void round_kv_kernel(
    const float* __restrict__ k, const float* __restrict__ v,
    __half* __restrict__ kr, __half* __restrict__ vr, int n4)
{
    const float* in  = blockIdx.z ? v : k;
    __half*      out = blockIdx.z ? vr : kr;
    int i = blockIdx.x * blockDim.x + threadIdx.x;
    if (i < n4) {
        float4 t = reinterpret_cast<const float4*>(in)[i];
        reinterpret_cast<__half2*>(out)[2 * i]     = __floats2half2_rn(t.x, t.y);
        reinterpret_cast<__half2*>(out)[2 * i + 1] = __floats2half2_rn(t.z, t.w);
    }
}

// ---------------- all-weights transpose + round: W[K][1024] -> Wt[1024][K] ----------------
__global__ __launch_bounds__(256) void transpose_all_kernel(
    const float* __restrict__ Wq, const float* __restrict__ Wo,
    const float* __restrict__ Wk, const float* __restrict__ Wv,
    __half* __restrict__ Wqt, __half* __restrict__ Wot,
    __half* __restrict__ Wkt, __half* __restrict__ Wvt)
{
    const int z = blockIdx.z;
    const int K = (z < 2) ? DMODEL : IMGM;
    if (blockIdx.y * 32 >= K) return;
    const float* in  = (z == 0) ? Wq : (z == 1) ? Wo : (z == 2) ? Wk : Wv;
    __half*      out = (z == 0) ? Wqt : (z == 1) ? Wot : (z == 2) ? Wkt : Wvt;

    __shared__ float tile[32][33];
    int k0 = blockIdx.y * 32, n0 = blockIdx.x * 32;
    int tx = threadIdx.x, ty = threadIdx.y;
#pragma unroll
    for (int i = ty; i < 32; i += 8)
        tile[i][tx] = in[(size_t)(k0 + i) * DMODEL + n0 + tx];
    __syncthreads();
#pragma unroll
    for (int i = ty; i < 32; i += 8)
        out[(size_t)(n0 + i) * K + k0 + tx] = __float2half_rn(tile[tx][i]);
}

// ---------------- fp16 GEMM: C[M,N] = (A[M,K] @ Bt[N,K]^T + bias) * oscale ----------------
// 128x128 tile, BK=64 halves, 3-stage cp.async ring, single barrier per k-iter.
#define GBM 128
#define GBN 128
#define GBK 64
#define GSTG 3
#define ASTR 72                       // halves per smem row (64 + 8 pad)
#define ATILE (GBM * ASTR)            // halves per stage (A or B)
#define GSMEM (2 * GSTG * ATILE * 2)  // bytes = 110592

template <bool HALF_OUT, bool DUAL>
__global__ __launch_bounds__(256, 2) void gemm_f16(
    const __half* __restrict__ A0, const __half* __restrict__ Bt0,
    const float* __restrict__ bias0, void* __restrict__ Cp0,
    const __half* __restrict__ A1, const __half* __restrict__ Bt1,
    const float* __restrict__ bias1, void* __restrict__ Cp1,
    int M, int N, int K, float oscale)
{
    const __half* A    = (DUAL && blockIdx.z) ? A1 : A0;
    const __half* Bt   = (DUAL && blockIdx.z) ? Bt1 : Bt0;
    const float*  bias = (DUAL && blockIdx.z) ? bias1 : bias0;
    void*         Cp   = (DUAL && blockIdx.z) ? Cp1 : Cp0;

    extern __shared__ __half smh[];
    __half* sA = smh;
    __half* sB = smh + GSTG * ATILE;
    const uint32_t sAb = (uint32_t)__cvta_generic_to_shared(sA);
    const uint32_t sBb = (uint32_t)__cvta_generic_to_shared(sB);

    const int tid = threadIdx.x;
    const int warp = tid >> 5, lane = tid & 31;
    const int wm = warp & 3, wn = warp >> 2;
    const int g = lane >> 2, c = lane & 3;
    const int m0 = blockIdx.y * GBM, n0 = blockIdx.x * GBN;

    auto load_stage = [&](int t, int s) {
#pragma unroll
        for (int p = 0; p < 4; p++) {
            int idx = tid + p * 256;
            int row = idx >> 3, ch = idx & 7;
            cp_async16(sA + s * ATILE + row * ASTR + ch * 8,
                       A + (size_t)(m0 + row) * K + t * GBK + ch * 8);
        }
#pragma unroll
        for (int p = 0; p < 4; p++) {
            int idx = tid + p * 256;
            int row = idx >> 3, ch = idx & 7;
            cp_async16(sB + s * ATILE + row * ASTR + ch * 8,
                       Bt + (size_t)(n0 + row) * K + t * GBK + ch * 8);
        }
    };

    float acc[2][8][4];
#pragma unroll
    for (int i = 0; i < 2; i++)
#pragma unroll
        for (int j = 0; j < 8; j++)
#pragma unroll
            for (int t = 0; t < 4; t++) acc[i][j][t] = 0.f;

    const int T = K / GBK;
    load_stage(0, 0); cp_commit();
    load_stage(1, 1); cp_commit();

    int slot = 0;
    for (int t = 0; t < T; t++) {
        cp_wait<1>();          // tile t landed
        __syncthreads();       // all warps done with iter t-1 (frees slot (t+2)%3)
        const uint32_t ab = sAb + slot * ATILE * 2;
        const uint32_t bb = sBb + slot * ATILE * 2;

#pragma unroll
        for (int kk = 0; kk < 4; kk++) {
            uint32_t af[2][4];
#pragma unroll
            for (int mt = 0; mt < 2; mt++) {
                int lrow = wm * 32 + mt * 16 + (lane & 15);
                int lcol = kk * 16 + (lane >> 4) * 8;
                ldm4(af[mt][0], af[mt][1], af[mt][2], af[mt][3],
                     ab + (lrow * ASTR + lcol) * 2);
            }
            uint32_t bf[8][2];
#pragma unroll
            for (int ng = 0; ng < 4; ng++) {
                int nrow = wn * 64 + ng * 16 + (lane & 7) + ((lane & 16) ? 8 : 0);
                int ncol = kk * 16 + ((lane >> 3) & 1) * 8;
                uint32_t r0, r1, r2, r3;
                ldm4(r0, r1, r2, r3, bb + (nrow * ASTR + ncol) * 2);
                bf[2 * ng][0] = r0;     bf[2 * ng][1] = r1;
                bf[2 * ng + 1][0] = r2; bf[2 * ng + 1][1] = r3;
            }
#pragma unroll
            for (int mt = 0; mt < 2; mt++)
#pragma unroll
                for (int nt = 0; nt < 8; nt++)
                    mma_f16(acc[mt][nt], af[mt], bf[nt][0], bf[nt][1]);
        }
        if (t + 2 < T) load_stage(t + 2, (t + 2) % 3);
        cp_commit();
        slot = (slot + 1 == GSTG) ? 0 : slot + 1;
    }

    // epilogue
#pragma unroll
    for (int mt = 0; mt < 2; mt++) {
        int row = m0 + wm * 32 + mt * 16 + g;
#pragma unroll
        for (int nt = 0; nt < 8; nt++) {
            int col = n0 + wn * 64 + nt * 8 + 2 * c;
            float2 bv = *reinterpret_cast<const float2*>(bias + col);
            float v0 = (acc[mt][nt][0] + bv.x) * oscale;
            float v1 = (acc[mt][nt][1] + bv.y) * oscale;
            float v2 = (acc[mt][nt][2] + bv.x) * oscale;
            float v3 = (acc[mt][nt][3] + bv.y) * oscale;
            if (HALF_OUT) {
                __half* C = (__half*)Cp;
                *reinterpret_cast<__half2*>(C + (size_t)row * N + col) =
                    __floats2half2_rn(v0, v1);
                *reinterpret_cast<__half2*>(C + (size_t)(row + 8) * N + col) =
                    __floats2half2_rn(v2, v3);
            } else {
                float* C = (float*)Cp;
                *reinterpret_cast<float2*>(C + (size_t)row * N + col) =
                    make_float2(v0, v1);
                *reinterpret_cast<float2*>(C + (size_t)(row + 8) * N + col) =
                    make_float2(v2, v3);
            }
        }
    }
}

// ---------------- fp16 flash attention ----------------
// Block = (b, h, 128 Q rows). 256 threads = 8 warps. KV tiles of 64 rows in a
// 3-stage cp.async ring. Q pre-scaled by 0.125*log2(e): base-2 softmax.
// P computed via ex2.approx.f16x2; row-sum l via extra mma with ones column.
#define FSTR 72                       // halves per smem row (64 + 8 pad)
#define KTILE (64 * FSTR)             // halves per K or V stage
#define FSTG 3
#define FLASH_SMEM ((2 * FSTG * KTILE + 128 * FSTR) * 2)  // 73728 B

__global__ __launch_bounds__(256, 2) void flash_f16(
    const __half* __restrict__ Qp, const __half* __restrict__ Kp,
    const __half* __restrict__ Vp, __half* __restrict__ AO)
{
    extern __shared__ __half smh[];
    __half* sK = smh;
    __half* sV = smh + FSTG * KTILE;
    __half* sQ = smh + 2 * FSTG * KTILE;
    const uint32_t sKb = (uint32_t)__cvta_generic_to_shared(sK);
    const uint32_t sVb = (uint32_t)__cvta_generic_to_shared(sV);
    const uint32_t sQb = (uint32_t)__cvta_generic_to_shared(sQ);

    const int tid = threadIdx.x;
    const int w = tid >> 5, lane = tid & 31;
    const int g = lane >> 2, c = lane & 3;
    const int q0 = blockIdx.x * 128, h = blockIdx.y, b = blockIdx.z;

    const __half* Qbase = Qp + ((size_t)(b * LQ_ + q0)) * DMODEL + h * DK_;
    const __half* Kbase = Kp + ((size_t)b * LKV_) * DMODEL + h * DK_;
    const __half* Vbase = Vp + ((size_t)b * LKV_) * DMODEL + h * DK_;

    auto load_kv = [&](int s, int kv0) {
#pragma unroll
        for (int p = 0; p < 2; p++) {
            int idx = tid + p * 256;
            int row = idx >> 3, ch = idx & 7;
            cp_async16(sK + s * KTILE + row * FSTR + ch * 8,
                       Kbase + (size_t)(kv0 + row) * DMODEL + ch * 8);
        }
#pragma unroll
        for (int p = 0; p < 2; p++) {
            int idx = tid + p * 256;
            int row = idx >> 3, ch = idx & 7;
            cp_async16(sV + s * KTILE + row * FSTR + ch * 8,
                       Vbase + (size_t)(kv0 + row) * DMODEL + ch * 8);
        }
    };

    // prologue: Q, kv0, kv1 (3 groups)
#pragma unroll
    for (int p = 0; p < 4; p++) {
        int idx = tid + p * 256;
        int row = idx >> 3, ch = idx & 7;
        cp_async16(sQ + row * FSTR + ch * 8,
                   Qbase + (size_t)row * DMODEL + ch * 8);
    }
    cp_commit();
    load_kv(0, 0);  cp_commit();
    load_kv(1, 64); cp_commit();

    cp_wait<2>();                 // Q ready
    __syncthreads();

    uint32_t qa[4][4];
#pragma unroll
    for (int kk = 0; kk < 4; kk++) {
        int lrow = w * 16 + (lane & 15);
        int lcol = kk * 16 + (lane >> 4) * 8;
        ldm4(qa[kk][0], qa[kk][1], qa[kk][2], qa[kk][3],
             sQb + (lrow * FSTR + lcol) * 2);
    }

    float o[8][4];
#pragma unroll
    for (int i = 0; i < 8; i++)
#pragma unroll
        for (int j = 0; j < 4; j++) o[i][j] = 0.f;
    float o9[4] = {0.f, 0.f, 0.f, 0.f};   // l rides here (ones-column mma)

    // B fragment of the ones column (n=0 of an n8 tile): lanes g==0 hold {1,1}
    const uint32_t ones = (g == 0) ? 0x3C003C00u : 0u;

    float m_r = -1e30f, m_8 = -1e30f;

    int slot = 0;
    for (int t = 0; t < LKV_ / 64; t++) {
        cp_wait<1>();             // KV tile t landed
        __syncthreads();          // all warps done with iter t-1
        const uint32_t kb  = sKb + slot * KTILE * 2;
        const uint32_t vbb = sVb + slot * KTILE * 2;

        // ---- S = Q @ K^T  (log2 domain) ----
        float s[8][4];
#pragma unroll
        for (int i = 0; i < 8; i++)
#pragma unroll
            for (int j = 0; j < 4; j++) s[i][j] = 0.f;
#pragma unroll
        for (int kk = 0; kk < 4; kk++) {
            uint32_t bf[8][2];
#pragma unroll
            for (int ng = 0; ng < 4; ng++) {
                int nrow = ng * 16 + (lane & 7) + ((lane & 16) ? 8 : 0);
                int ncol = kk * 16 + ((lane >> 3) & 1) * 8;
                uint32_t r0, r1, r2, r3;
                ldm4(r0, r1, r2, r3, kb + (nrow * FSTR + ncol) * 2);
                bf[2 * ng][0] = r0;     bf[2 * ng][1] = r1;
                bf[2 * ng + 1][0] = r2; bf[2 * ng + 1][1] = r3;
            }
#pragma unroll
            for (int nt = 0; nt < 8; nt++)
                mma_f16(s[nt], qa[kk], bf[nt][0], bf[nt][1]);
        }

        // ---- online softmax (base-2), P via f16x2 exp ----
        float cr = -1e30f, c8 = -1e30f;
#pragma unroll
        for (int nt = 0; nt < 8; nt++) {
            cr = fmaxf(cr, fmaxf(s[nt][0], s[nt][1]));
            c8 = fmaxf(c8, fmaxf(s[nt][2], s[nt][3]));
        }
        cr = fmaxf(cr, __shfl_xor_sync(0xffffffffu, cr, 1));
        cr = fmaxf(cr, __shfl_xor_sync(0xffffffffu, cr, 2));
        c8 = fmaxf(c8, __shfl_xor_sync(0xffffffffu, c8, 1));
        c8 = fmaxf(c8, __shfl_xor_sync(0xffffffffu, c8, 2));
        float mn_r = fmaxf(m_r, cr);
        float mn_8 = fmaxf(m_8, c8);
        float alpha_r = exp2f(m_r - mn_r);
        float alpha_8 = exp2f(m_8 - mn_8);
        m_r = mn_r; m_8 = mn_8;

        uint32_t P[8][2];
#pragma unroll
        for (int nt = 0; nt < 8; nt++) {
            P[nt][0] = h2exp2(packh2(s[nt][0] - m_r, s[nt][1] - m_r));
            P[nt][1] = h2exp2(packh2(s[nt][2] - m_8, s[nt][3] - m_8));
            o[nt][0] *= alpha_r; o[nt][1] *= alpha_r;
            o[nt][2] *= alpha_8; o[nt][3] *= alpha_8;
        }
        o9[0] *= alpha_r; o9[2] *= alpha_8;

        // ---- O += P @ V ; l += P @ 1 ----
#pragma unroll
        for (int kk = 0; kk < 4; kk++) {
            uint32_t pa[4];
            pa[0] = P[2 * kk][0];
            pa[1] = P[2 * kk][1];
            pa[2] = P[2 * kk + 1][0];
            pa[3] = P[2 * kk + 1][1];
            uint32_t vf[8][2];
#pragma unroll
            for (int ng = 0; ng < 4; ng++) {
                int vrow = kk * 16 + (lane & 7) + ((lane & 8) ? 8 : 0);
                int vcol = ng * 16 + ((lane & 16) ? 8 : 0);
                uint32_t r0, r1, r2, r3;
                ldm4t(r0, r1, r2, r3, vbb + (vrow * FSTR + vcol) * 2);
                vf[2 * ng][0] = r0;     vf[2 * ng][1] = r1;
                vf[2 * ng + 1][0] = r2; vf[2 * ng + 1][1] = r3;
            }
#pragma unroll
            for (int nt = 0; nt < 8; nt++)
                mma_f16(o[nt], pa, vf[nt][0], vf[nt][1]);
            mma_f16(o9, pa, ones, ones);
        }
        if (t + 2 < LKV_ / 64) load_kv((t + 2) % 3, (t + 2) * 64);
        cp_commit();
        slot = (slot + 1 == FSTG) ? 0 : slot + 1;
    }

    // ---- l from the ones column (col 0 lives in c==0 lanes) ----
    int src = lane & ~3;
    float l_r = __shfl_sync(0xffffffffu, o9[0], src);
    float l_8 = __shfl_sync(0xffffffffu, o9[2], src);

    // ---- normalize, write AO half in concat layout ----
    float inv_r = 1.f / l_r, inv_8 = 1.f / l_8;
    int qg = q0 + w * 16 + g;
    __half* Obase = AO + ((size_t)(b * LQ_ + qg)) * DMODEL + h * DK_;
#pragma unroll
    for (int nt = 0; nt < 8; nt++) {
        int col = nt * 8 + 2 * c;
        *reinterpret_cast<__half2*>(Obase + col) =
            __floats2half2_rn(o[nt][0] * inv_r, o[nt][1] * inv_r);
        *reinterpret_cast<__half2*>(Obase + (size_t)8 * DMODEL + col) =
            __floats2half2_rn(o[nt][2] * inv_8, o[nt][3] * inv_8);
    }
}

// ---------------- launch ----------------
extern "C" void kernel_launch(void* const* d_in, const int* in_sizes, int n_in,
                              void* d_out, int out_size)
{
    (void)in_sizes; (void)n_in; (void)out_size;
    const float* q  = (const float*)d_in[0];
    const float* k  = (const float*)d_in[1];
    const float* v  = (const float*)d_in[2];
    const float* Wq = (const float*)d_in[3];
    const float* bq = (const float*)d_in[4];
    const float* Wk = (const float*)d_in[5];
    const float* bk = (const float*)d_in[6];
    const float* Wv = (const float*)d_in[7];
    const float* bv = (const float*)d_in[8];
    const float* Wo = (const float*)d_in[9];
    const float* bo = (const float*)d_in[10];
    float* out = (float*)d_out;

    __half *qr, *kr, *vr, *Wqt, *Wkt, *Wvt, *Wot, *Qp, *Kp, *Vp, *AO;
    cudaGetSymbolAddress((void**)&qr,  g_qr);
    cudaGetSymbolAddress((void**)&kr,  g_kr);
    cudaGetSymbolAddress((void**)&vr,  g_vr);
    cudaGetSymbolAddress((void**)&Wqt, g_Wqt);
    cudaGetSymbolAddress((void**)&Wkt, g_Wkt);
    cudaGetSymbolAddress((void**)&Wvt, g_Wvt);
    cudaGetSymbolAddress((void**)&Wot, g_Wot);
    cudaGetSymbolAddress((void**)&Qp,  g_Qp);
    cudaGetSymbolAddress((void**)&Kp,  g_Kp);
    cudaGetSymbolAddress((void**)&Vp,  g_Vp);
    cudaGetSymbolAddress((void**)&AO,  g_AO);

    cudaFuncSetAttribute((const void*)gemm_f16<true, false>,
                         cudaFuncAttributeMaxDynamicSharedMemorySize, GSMEM);
    cudaFuncSetAttribute((const void*)gemm_f16<true, true>,
                         cudaFuncAttributeMaxDynamicSharedMemorySize, GSMEM);
    cudaFuncSetAttribute((const void*)gemm_f16<false, false>,
                         cudaFuncAttributeMaxDynamicSharedMemorySize, GSMEM);
    cudaFuncSetAttribute((const void*)flash_f16,
                         cudaFuncAttributeMaxDynamicSharedMemorySize, FLASH_SMEM);

    // launch 1: round q
    {
        int n4 = (int)((size_t)B_SZ * LQ_ * DMODEL / 4);
        round_half_kernel<<<(n4 + 255) / 256, 256>>>(q, qr, n4);
    }
    // launch 2: round k and v together
    {
        int n4 = (int)((size_t)B_SZ * LKV_ * IMGM / 4);
        round_kv_kernel<<<dim3((n4 + 255) / 256, 1, 2), 256>>>(k, v, kr, vr, n4);
    }
    // launch 3: all weight transposes
    transpose_all_kernel<<<dim3(DMODEL / 32, DMODEL / 32, 4), dim3(32, 8)>>>(
        Wq, Wo, Wk, Wv, Wqt, Wot, Wkt, Wvt);

    const float QSCALE = 0.125f * 1.4426950408889634f;  // (1/sqrt(64)) * log2(e)

    // launch 4: Q projection (pre-scaled for base-2 softmax)
    gemm_f16<true, false><<<dim3(DMODEL / GBN, (B_SZ * LQ_) / GBM), 256, GSMEM>>>(
        qr, Wqt, bq, Qp, nullptr, nullptr, nullptr, nullptr,
        B_SZ * LQ_, DMODEL, DMODEL, QSCALE);

    // launch 5: K and V projections fused (z selects operand set)
    gemm_f16<true, true><<<dim3(DMODEL / GBN, (B_SZ * LKV_) / GBM, 2), 256, GSMEM>>>(
        kr, Wkt, bk, Kp, vr, Wvt, bv, Vp,
        B_SZ * LKV_, DMODEL, IMGM, 1.0f);

    // launch 6: attention
    flash_f16<<<dim3(LQ_ / 128, HEADS_, B_SZ), 256, FLASH_SMEM>>>(
        Qp, Kp, Vp, AO);

    // launch 7: output projection (fp32 out)
    gemm_f16<false, false><<<dim3(DMODEL / GBN, (B_SZ * LQ_) / GBM), 256, GSMEM>>>(
        AO, Wot, bo, out, nullptr, nullptr, nullptr, nullptr,
        B_SZ * LQ_, DMODEL, DMODEL, 1.0f);
}